// round 1
// baseline (speedup 1.0000x reference)
#include <cuda_runtime.h>
#include <math.h>

#define NNODES 200000
#define NEDGES 800000
#define NG     4096
#define DCELL  954
#define F      128
#define BN_EPS 1e-5f

// ---------------- scratch (static device globals; no allocs allowed) ----------
__device__ float g_bufA[(size_t)NNODES * F];   // 102.4 MB
__device__ float g_bufB[(size_t)NNODES * F];   // 102.4 MB
__device__ float g_dinv[NNODES];               // deg, then rsqrt(deg)
__device__ float g_cell[(size_t)NG * F];
__device__ float g_stats[3 * 2 * F];           // 3 BN uses: [sum(128) | sumsq(128)] each
__device__ int   g_start[NG + 1];

// ---------------- init ---------------------------------------------------------
__global__ void init_kernel() {
    int i = blockIdx.x * blockDim.x + threadIdx.x;
    if (i < NNODES) g_dinv[i] = 1.0f;            // self-loop contributes 1 to in-degree
    if (i < 3 * 2 * F) g_stats[i] = 0.0f;
    if (i == 0) g_start[NG] = NNODES;
}

__global__ void deg_kernel(const int* __restrict__ dst) {
    int e = blockIdx.x * blockDim.x + threadIdx.x;
    if (e < NEDGES) atomicAdd(&g_dinv[dst[e]], 1.0f);
}

__global__ void rsqrt_kernel() {
    int i = blockIdx.x * blockDim.x + threadIdx.x;
    if (i < NNODES) g_dinv[i] = rsqrtf(g_dinv[i]);   // deg >= 1 always (self-loop)
}

// ---------------- generic tiled GEMM: C[M,128] = A[M,K] @ B[K,128] (+bias,act) --
// act: 0 = none, 1 = relu, 2 = tanh
__global__ void gemm128(const float* __restrict__ A, const float* __restrict__ B,
                        const float* __restrict__ bias, float* __restrict__ C,
                        int M, int K, int act)
{
    __shared__ float As[32][65];    // +1 pad: conflict-free transposed store
    __shared__ float Bs[32][128];

    const int tid = threadIdx.x;            // 256 threads
    const int m0  = blockIdx.x * 64;
    const int tx  = tid & 15;
    const int ty  = tid >> 4;

    float acc[4][8];
#pragma unroll
    for (int i = 0; i < 4; i++)
#pragma unroll
        for (int j = 0; j < 8; j++) acc[i][j] = 0.0f;

    for (int kk = 0; kk < K; kk += 32) {
        // A tile: 64 rows x 32 k, coalesced global (32 consecutive k per warp)
#pragma unroll
        for (int i = 0; i < 8; i++) {
            int idx = tid + i * 256;
            int m = idx >> 5, k = idx & 31;
            int gm = m0 + m, gk = kk + k;
            float v = 0.0f;
            if (gm < M && gk < K) v = A[(size_t)gm * K + gk];
            As[k][m] = v;
        }
        // B tile: 32 k x 128 n
#pragma unroll
        for (int i = 0; i < 16; i++) {
            int idx = tid + i * 256;
            int k = idx >> 7, n = idx & 127;
            int gk = kk + k;
            float v = 0.0f;
            if (gk < K) v = B[(size_t)gk * 128 + n];
            Bs[k][n] = v;
        }
        __syncthreads();

#pragma unroll
        for (int k = 0; k < 32; k++) {
            float a[4], b[8];
#pragma unroll
            for (int i = 0; i < 4; i++) a[i] = As[k][ty * 4 + i];
#pragma unroll
            for (int j = 0; j < 8; j++) b[j] = Bs[k][tx + 16 * j];
#pragma unroll
            for (int i = 0; i < 4; i++)
#pragma unroll
                for (int j = 0; j < 8; j++) acc[i][j] = fmaf(a[i], b[j], acc[i][j]);
        }
        __syncthreads();
    }

#pragma unroll
    for (int i = 0; i < 4; i++) {
        int gm = m0 + ty * 4 + i;
        if (gm >= M) continue;
#pragma unroll
        for (int j = 0; j < 8; j++) {
            int n = tx + 16 * j;
            float v = acc[i][j];
            if (bias) v += bias[n];
            if (act == 1)      v = fmaxf(v, 0.0f);
            else if (act == 2) v = tanhf(v);
            C[(size_t)gm * 128 + n] = v;
        }
    }
}

// ---------------- GCN aggregation ----------------------------------------------
// self-loop term: agg[i] = h[i] * dinv[i]^2
__global__ void selfinit_kernel(const float* __restrict__ h, float* __restrict__ agg) {
    int i = blockIdx.x * blockDim.x + threadIdx.x;
    if (i < NNODES * F) {
        int node = i >> 7;
        float di = g_dinv[node];
        agg[i] = h[i] * di * di;
    }
}

// one warp per edge; 32 lanes each do one red.global.add.v4.f32 (L2-resident target)
__global__ void scatter_kernel(const float* __restrict__ h, float* __restrict__ agg,
                               const int* __restrict__ src, const int* __restrict__ dst)
{
    int w    = (blockIdx.x * blockDim.x + threadIdx.x) >> 5;
    int lane = threadIdx.x & 31;
    if (w >= NEDGES) return;
    int s = 0, d = 0;
    if (lane == 0) { s = src[w]; d = dst[w]; }
    s = __shfl_sync(0xffffffffu, s, 0);
    d = __shfl_sync(0xffffffffu, d, 0);
    float norm = g_dinv[s] * g_dinv[d];
    float4 v = ((const float4*)(h + (size_t)s * F))[lane];
    v.x *= norm; v.y *= norm; v.z *= norm; v.w *= norm;
    float* a = agg + (size_t)d * F + lane * 4;
    asm volatile("red.global.add.v4.f32 [%0], {%1,%2,%3,%4};"
                 :: "l"(a), "f"(v.x), "f"(v.y), "f"(v.z), "f"(v.w) : "memory");
}

// ---------------- BatchNorm (training-mode batch stats) -------------------------
// t = (relu? max(in+bias,0) : in); stats[d] += sum, stats[128+d] += sumsq
__global__ void bn_stats_kernel(const float* __restrict__ in, const float* __restrict__ bias,
                                int relu, float* __restrict__ stats, int M)
{
    int d = threadIdx.x;   // 128 threads
    float b = bias ? bias[d] : 0.0f;
    float s = 0.0f, q = 0.0f;
    for (int r = blockIdx.x; r < M; r += gridDim.x) {
        float v = in[(size_t)r * F + d] + b;
        if (relu) v = fmaxf(v, 0.0f);
        s += v;
        q += v * v;
    }
    atomicAdd(&stats[d], s);
    atomicAdd(&stats[F + d], q);
}

__global__ void bn_apply_kernel(const float* __restrict__ in, const float* __restrict__ bias,
                                int relu, const float* __restrict__ stats,
                                const float* __restrict__ gamma, const float* __restrict__ beta,
                                float* __restrict__ out, int M)
{
    int i = blockIdx.x * blockDim.x + threadIdx.x;
    if (i >= M * F) return;
    int d = i & 127;
    float v = in[i] + (bias ? bias[d] : 0.0f);
    if (relu) v = fmaxf(v, 0.0f);
    float invM = 1.0f / (float)M;
    float m   = stats[d] * invM;
    float var = stats[F + d] * invM - m * m;
    out[i] = gamma[d] * (v - m) * rsqrtf(var + BN_EPS) + beta[d];
}

// ---------------- segment boundaries + segment max ------------------------------
__global__ void bounds_kernel(const int* __restrict__ ib) {
    int i = blockIdx.x * blockDim.x + threadIdx.x;
    if (i >= NNODES) return;
    if (i == 0) g_start[ib[0]] = 0;
    else {
        int g = ib[i];
        if (ib[i - 1] != g) g_start[g] = i;
    }
}

__global__ void segmax_kernel(const float* __restrict__ h, float* __restrict__ out) {
    int idx = blockIdx.x * blockDim.x + threadIdx.x;
    if (idx >= NG * F) return;
    int g = idx >> 7, d = idx & 127;
    int s = g_start[g], e = g_start[g + 1];
    float m = -3.402823466e38f;
    for (int r = s; r < e; r++)
        m = fmaxf(m, h[(size_t)r * F + d]);
    out[idx] = m;
}

// ---------------- launch ---------------------------------------------------------
extern "C" void kernel_launch(void* const* d_in, const int* in_sizes, int n_in,
                              void* d_out, int out_size)
{
    const float* x      = (const float*)d_in[0];
    const int*   eidx   = (const int*)  d_in[1];   // [2,E] -> src=eidx[0:E], dst=eidx[E:2E]
    const int*   ibatch = (const int*)  d_in[2];
    const float* gexpr  = (const float*)d_in[3];
    const float* W1  = (const float*)d_in[4];
    const float* b1  = (const float*)d_in[5];
    const float* g1  = (const float*)d_in[6];
    const float* be1 = (const float*)d_in[7];
    const float* W2  = (const float*)d_in[8];
    const float* b2  = (const float*)d_in[9];
    const float* g2  = (const float*)d_in[10];
    const float* be2 = (const float*)d_in[11];
    const float* Wc1 = (const float*)d_in[12];
    const float* bc1 = (const float*)d_in[13];
    const float* gc  = (const float*)d_in[14];
    const float* bec = (const float*)d_in[15];
    const float* Wc2 = (const float*)d_in[16];
    const float* bc2 = (const float*)d_in[17];
    float* out = (float*)d_out;

    const int* src = eidx;
    const int* dst = eidx + NEDGES;

    float* bufA;  cudaGetSymbolAddress((void**)&bufA,  g_bufA);
    float* bufB;  cudaGetSymbolAddress((void**)&bufB,  g_bufB);
    float* cell;  cudaGetSymbolAddress((void**)&cell,  g_cell);
    float* stats; cudaGetSymbolAddress((void**)&stats, g_stats);

    const int T = 256;
    int gN   = (NNODES + T - 1) / T;          // 782
    int gE   = (NEDGES + T - 1) / T;          // 3125
    int gNF  = (NNODES * F + T - 1) / T;      // 100000
    int gEW  = (NEDGES * 32 + T - 1) / T;     // 100000 (warp per edge)
    int gGF  = (NG * F + T - 1) / T;          // 2048

    // degrees -> dinv
    init_kernel<<<gN, T>>>();
    deg_kernel<<<gE, T>>>(dst);
    rsqrt_kernel<<<gN, T>>>();

    // ---- drug layer 1: h1 = x@W1 ; agg1 = sum norm*h1 ; bn(relu(agg1+b1)) -> A
    gemm128<<<(NNODES + 63) / 64, 256>>>(x, W1, nullptr, bufA, NNODES, 128, 0);
    selfinit_kernel<<<gNF, T>>>(bufA, bufB);
    scatter_kernel<<<gEW, T>>>(bufA, bufB, src, dst);
    bn_stats_kernel<<<2048, 128>>>(bufB, b1, 1, stats + 0, NNODES);
    bn_apply_kernel<<<gNF, T>>>(bufB, b1, 1, stats + 0, g1, be1, bufA, NNODES);

    // ---- drug layer 2: h2 = A@W2 ; agg2 ; bn(relu(agg2+b2)) -> B
    gemm128<<<(NNODES + 63) / 64, 256>>>(bufA, W2, nullptr, bufB, NNODES, 128, 0);
    selfinit_kernel<<<gNF, T>>>(bufB, bufA);
    scatter_kernel<<<gEW, T>>>(bufB, bufA, src, dst);
    bn_stats_kernel<<<2048, 128>>>(bufA, b2, 1, stats + 256, NNODES);
    bn_apply_kernel<<<gNF, T>>>(bufA, b2, 1, stats + 256, g2, be2, bufB, NNODES);

    // ---- global max pool -> out[0 : G*F)
    bounds_kernel<<<gN, T>>>(ibatch);
    segmax_kernel<<<gGF, T>>>(bufB, out);

    // ---- cell branch -> out[G*F : 2*G*F)
    gemm128<<<(NG + 63) / 64, 256>>>(gexpr, Wc1, bc1, cell, NG, DCELL, 2);   // tanh
    bn_stats_kernel<<<512, 128>>>(cell, nullptr, 0, stats + 512, NG);
    bn_apply_kernel<<<gGF, T>>>(cell, nullptr, 0, stats + 512, gc, bec, cell, NG);
    gemm128<<<(NG + 63) / 64, 256>>>(cell, Wc2, bc2, out + (size_t)NG * F, NG, 128, 1); // relu
}

// round 2
// speedup vs baseline: 1.2187x; 1.2187x over previous
#include <cuda_runtime.h>
#include <math.h>

#define NNODES 200000
#define NEDGES 800000
#define NG     4096
#define DCELL  954
#define F      128
#define BN_EPS 1e-5f
#define NBLK   782          // ceil(NNODES/256)

// ---------------- scratch (static device globals) ------------------------------
__device__ float g_bufA[(size_t)NNODES * F];   // 102.4 MB
__device__ float g_bufB[(size_t)NNODES * F];   // 102.4 MB
__device__ float g_dinv[NNODES];
__device__ int   g_deg[NNODES];
__device__ int   g_cursor[NNODES];
__device__ int   g_csr_ptr[NNODES + 1];
__device__ int   g_csr_src[NEDGES];
__device__ int   g_blocksums[1024];
__device__ int   g_blockoff[1024];
__device__ float g_cell[(size_t)NG * F];
__device__ float g_sums[3 * 2 * F];            // 3 BN uses: [sum | sumsq]
__device__ float g_aff[2 * 2 * F];             // layers 1,2: [scale | shift]
__device__ int   g_start[NG + 1];

// ---------------- init ----------------------------------------------------------
__global__ void init_kernel() {
    int i = blockIdx.x * blockDim.x + threadIdx.x;
    if (i < NNODES) { g_deg[i] = 0; g_cursor[i] = 0; }
    if (i < 3 * 2 * F) g_sums[i] = 0.0f;
}

__global__ void deg_kernel(const int* __restrict__ dst) {
    int e = blockIdx.x * blockDim.x + threadIdx.x;
    if (e < NEDGES) atomicAdd(&g_deg[dst[e]], 1);
}

__global__ void dinv_kernel() {
    int i = blockIdx.x * blockDim.x + threadIdx.x;
    if (i < NNODES) g_dinv[i] = rsqrtf((float)g_deg[i] + 1.0f);  // +1 self-loop
}

// ---------------- CSR build: scan + fill ----------------------------------------
__global__ void scan1_kernel() {
    __shared__ int sh[256];
    int i = blockIdx.x * 256 + threadIdx.x;
    int v = (i < NNODES) ? g_deg[i] : 0;
    sh[threadIdx.x] = v;
    __syncthreads();
#pragma unroll
    for (int off = 1; off < 256; off <<= 1) {
        int t = (threadIdx.x >= off) ? sh[threadIdx.x - off] : 0;
        __syncthreads();
        sh[threadIdx.x] += t;
        __syncthreads();
    }
    if (i < NNODES) g_csr_ptr[i] = sh[threadIdx.x] - v;   // exclusive (local)
    if (threadIdx.x == 255) g_blocksums[blockIdx.x] = sh[255];
}

__global__ void scan2_kernel() {
    __shared__ int sh[1024];
    int t = threadIdx.x;
    int v = (t < NBLK) ? g_blocksums[t] : 0;
    sh[t] = v;
    __syncthreads();
#pragma unroll
    for (int off = 1; off < 1024; off <<= 1) {
        int u = (t >= off) ? sh[t - off] : 0;
        __syncthreads();
        sh[t] += u;
        __syncthreads();
    }
    if (t < NBLK) g_blockoff[t] = sh[t] - v;              // exclusive block offsets
}

__global__ void scan3_kernel() {
    int i = blockIdx.x * blockDim.x + threadIdx.x;
    if (i < NNODES) g_csr_ptr[i] += g_blockoff[i >> 8];
    if (i == 0) g_csr_ptr[NNODES] = NEDGES;
}

__global__ void fill_kernel(const int* __restrict__ src, const int* __restrict__ dst) {
    int e = blockIdx.x * blockDim.x + threadIdx.x;
    if (e >= NEDGES) return;
    int d = dst[e];
    int pos = g_csr_ptr[d] + atomicAdd(&g_cursor[d], 1);
    g_csr_src[pos] = src[e];
}

// ---------------- GCN aggregation: gather-by-node (no atomics) -------------------
// agg[i] = dinv[i]^2 * h[i] + sum_{e: dst=i} dinv[i]*dinv[src] * h[src]
__global__ void gather_kernel(const float* __restrict__ h, float* __restrict__ agg) {
    int node = blockIdx.x * 8 + (threadIdx.x >> 5);
    int lane = threadIdx.x & 31;
    if (node >= NNODES) return;
    int beg = g_csr_ptr[node];
    int end = g_csr_ptr[node + 1];
    float di = g_dinv[node];
    const float4* hv = (const float4*)h;
    float4 acc = hv[(size_t)node * 32 + lane];
    float sn = di * di;
    acc.x *= sn; acc.y *= sn; acc.z *= sn; acc.w *= sn;
    int e = beg;
    for (; e + 1 < end; e += 2) {
        int s0 = __ldg(&g_csr_src[e]);
        int s1 = __ldg(&g_csr_src[e + 1]);
        float n0 = di * g_dinv[s0];
        float n1 = di * g_dinv[s1];
        float4 v0 = hv[(size_t)s0 * 32 + lane];
        float4 v1 = hv[(size_t)s1 * 32 + lane];
        acc.x = fmaf(v0.x, n0, acc.x); acc.y = fmaf(v0.y, n0, acc.y);
        acc.z = fmaf(v0.z, n0, acc.z); acc.w = fmaf(v0.w, n0, acc.w);
        acc.x = fmaf(v1.x, n1, acc.x); acc.y = fmaf(v1.y, n1, acc.y);
        acc.z = fmaf(v1.z, n1, acc.z); acc.w = fmaf(v1.w, n1, acc.w);
    }
    if (e < end) {
        int s0 = __ldg(&g_csr_src[e]);
        float n0 = di * g_dinv[s0];
        float4 v0 = hv[(size_t)s0 * 32 + lane];
        acc.x = fmaf(v0.x, n0, acc.x); acc.y = fmaf(v0.y, n0, acc.y);
        acc.z = fmaf(v0.z, n0, acc.z); acc.w = fmaf(v0.w, n0, acc.w);
    }
    ((float4*)agg)[(size_t)node * 32 + lane] = acc;
}

// ---------------- GEMM: C[M,128] = A'[M,K] @ B[K,128] ---------------------------
// A' = A optionally transformed per element: relu(A+prebias[k])*aff[k] + aff[F+k]
// act: 0 none, 1 relu, 2 tanh. 128x128 tile, 256 threads, 8x8 per thread.
__global__ __launch_bounds__(256) void gemm128(
    const float* __restrict__ A, const float* __restrict__ B,
    const float* __restrict__ bias, float* __restrict__ C,
    int M, int K, int act,
    const float* __restrict__ prebias, const float* __restrict__ aff)
{
    __shared__ float As[16][132];   // [k][m], padded
    __shared__ float Bs[16][128];   // [k][n]

    const int tid = threadIdx.x;
    const int m0  = blockIdx.x * 128;
    const int tn  = tid & 15;
    const int tm  = tid >> 4;

    float acc[8][8];
#pragma unroll
    for (int i = 0; i < 8; i++)
#pragma unroll
        for (int j = 0; j < 8; j++) acc[i][j] = 0.0f;

    const int arow = tid >> 4;   // 0..15
    const int acol = tid & 15;   // k within panel
    const int brow = tid >> 7;   // 0..1
    const int bcol = tid & 127;

    for (int kk = 0; kk < K; kk += 16) {
        // A panel: 128 rows x 16 k
#pragma unroll
        for (int p = 0; p < 8; p++) {
            int m  = p * 16 + arow;
            int gk = kk + acol;
            int gm = m0 + m;
            float v = 0.0f;
            if (gm < M && gk < K) v = A[(size_t)gm * K + gk];
            if (prebias) {
                float t = fmaxf(v + prebias[gk], 0.0f);
                v = fmaf(t, aff[gk], aff[F + gk]);
            }
            As[acol][m] = v;
        }
        // B panel: 16 k x 128 n
#pragma unroll
        for (int q = 0; q < 8; q++) {
            int k  = q * 2 + brow;
            int gk = kk + k;
            Bs[k][bcol] = (gk < K) ? B[(size_t)gk * 128 + bcol] : 0.0f;
        }
        __syncthreads();

#pragma unroll
        for (int k = 0; k < 16; k++) {
            float4 a0 = *(const float4*)&As[k][tm * 8];
            float4 a1 = *(const float4*)&As[k][tm * 8 + 4];
            float4 b0 = *(const float4*)&Bs[k][tn * 8];
            float4 b1 = *(const float4*)&Bs[k][tn * 8 + 4];
            float a[8] = {a0.x, a0.y, a0.z, a0.w, a1.x, a1.y, a1.z, a1.w};
            float b[8] = {b0.x, b0.y, b0.z, b0.w, b1.x, b1.y, b1.z, b1.w};
#pragma unroll
            for (int i = 0; i < 8; i++)
#pragma unroll
                for (int j = 0; j < 8; j++)
                    acc[i][j] = fmaf(a[i], b[j], acc[i][j]);
        }
        __syncthreads();
    }

#pragma unroll
    for (int i = 0; i < 8; i++) {
        int gm = m0 + tm * 8 + i;
        if (gm >= M) continue;
        float o[8];
#pragma unroll
        for (int j = 0; j < 8; j++) {
            int n = tn * 8 + j;
            float v = acc[i][j];
            if (bias) v += bias[n];
            if (act == 1)      v = fmaxf(v, 0.0f);
            else if (act == 2) v = tanhf(v);
            o[j] = v;
        }
        float4* cp = (float4*)&C[(size_t)gm * 128 + tn * 8];
        cp[0] = make_float4(o[0], o[1], o[2], o[3]);
        cp[1] = make_float4(o[4], o[5], o[6], o[7]);
    }
}

// ---------------- BatchNorm pieces -----------------------------------------------
__global__ void bn_stats_kernel(const float* __restrict__ in, const float* __restrict__ bias,
                                int relu, float* __restrict__ sums, int M)
{
    int d = threadIdx.x;   // 128 threads
    float b = bias ? bias[d] : 0.0f;
    float s = 0.0f, q = 0.0f;
    for (int r = blockIdx.x; r < M; r += gridDim.x) {
        float v = in[(size_t)r * F + d] + b;
        if (relu) v = fmaxf(v, 0.0f);
        s += v;
        q += v * v;
    }
    atomicAdd(&sums[d], s);
    atomicAdd(&sums[F + d], q);
}

__global__ void finalize_kernel(const float* __restrict__ sums, float invM,
                                const float* __restrict__ gamma, const float* __restrict__ beta,
                                float* __restrict__ aff)
{
    int d = threadIdx.x;  // 128
    float m = sums[d] * invM;
    float var = sums[F + d] * invM - m * m;
    float r = rsqrtf(var + BN_EPS);
    float sc = gamma[d] * r;
    aff[d]     = sc;
    aff[F + d] = beta[d] - sc * m;
}

// cell branch: classic apply (small)
__global__ void bn_apply_kernel(const float* __restrict__ in, const float* __restrict__ sums,
                                const float* __restrict__ gamma, const float* __restrict__ beta,
                                float* __restrict__ out, int M)
{
    int i = blockIdx.x * blockDim.x + threadIdx.x;
    if (i >= M * F) return;
    int d = i & 127;
    float invM = 1.0f / (float)M;
    float m   = sums[d] * invM;
    float var = sums[F + d] * invM - m * m;
    out[i] = gamma[d] * (in[i] - m) * rsqrtf(var + BN_EPS) + beta[d];
}

// ---------------- segment boundaries + fused bn+segmax ---------------------------
__global__ void bounds_kernel(const int* __restrict__ ib) {
    int i = blockIdx.x * blockDim.x + threadIdx.x;
    if (i >= NNODES) return;
    if (i == 0) { g_start[ib[0]] = 0; g_start[NG] = NNODES; }
    else {
        int g = ib[i];
        if (ib[i - 1] != g) g_start[g] = i;
    }
}

// reads raw agg2, applies relu(v+b)*scale+shift inline, then per-segment max
__global__ void segmax_kernel(const float* __restrict__ h, const float* __restrict__ bias,
                              const float* __restrict__ aff, float* __restrict__ out)
{
    int idx = blockIdx.x * blockDim.x + threadIdx.x;
    if (idx >= NG * F) return;
    int g = idx >> 7, d = idx & 127;
    int s = g_start[g], e = g_start[g + 1];
    float b = bias[d], sc = aff[d], sh = aff[F + d];
    float m = -3.402823466e38f;
    for (int r = s; r < e; r++) {
        float v = fmaxf(h[(size_t)r * F + d] + b, 0.0f);
        m = fmaxf(m, fmaf(v, sc, sh));
    }
    out[idx] = m;
}

// ---------------- launch -----------------------------------------------------------
extern "C" void kernel_launch(void* const* d_in, const int* in_sizes, int n_in,
                              void* d_out, int out_size)
{
    const float* x      = (const float*)d_in[0];
    const int*   eidx   = (const int*)  d_in[1];
    const int*   ibatch = (const int*)  d_in[2];
    const float* gexpr  = (const float*)d_in[3];
    const float* W1  = (const float*)d_in[4];
    const float* b1  = (const float*)d_in[5];
    const float* g1  = (const float*)d_in[6];
    const float* be1 = (const float*)d_in[7];
    const float* W2  = (const float*)d_in[8];
    const float* b2  = (const float*)d_in[9];
    const float* g2  = (const float*)d_in[10];
    const float* be2 = (const float*)d_in[11];
    const float* Wc1 = (const float*)d_in[12];
    const float* bc1 = (const float*)d_in[13];
    const float* gc  = (const float*)d_in[14];
    const float* bec = (const float*)d_in[15];
    const float* Wc2 = (const float*)d_in[16];
    const float* bc2 = (const float*)d_in[17];
    float* out = (float*)d_out;

    const int* src = eidx;
    const int* dst = eidx + NEDGES;

    float* bufA; cudaGetSymbolAddress((void**)&bufA, g_bufA);
    float* bufB; cudaGetSymbolAddress((void**)&bufB, g_bufB);
    float* cell; cudaGetSymbolAddress((void**)&cell, g_cell);
    float* sums; cudaGetSymbolAddress((void**)&sums, g_sums);
    float* aff;  cudaGetSymbolAddress((void**)&aff,  g_aff);

    const int T = 256;
    int gN  = (NNODES + T - 1) / T;
    int gE  = (NEDGES + T - 1) / T;
    int gGF = (NG * F + T - 1) / T;
    int gGather = (NNODES + 7) / 8;
    int gGemmN  = (NNODES + 127) / 128;
    int gGemmG  = (NG + 127) / 128;

    // degrees + CSR (shared by both layers)
    init_kernel<<<gN, T>>>();
    deg_kernel<<<gE, T>>>(dst);
    dinv_kernel<<<gN, T>>>();
    scan1_kernel<<<NBLK, 256>>>();
    scan2_kernel<<<1, 1024>>>();
    scan3_kernel<<<gN, T>>>();
    fill_kernel<<<gE, T>>>(src, dst);

    // ---- drug layer 1: h1 = x@W1 -> A ; gather -> B ; stats/finalize
    gemm128<<<gGemmN, 256>>>(x, W1, nullptr, bufA, NNODES, 128, 0, nullptr, nullptr);
    gather_kernel<<<gGather, 256>>>(bufA, bufB);
    bn_stats_kernel<<<2048, 128>>>(bufB, b1, 1, sums + 0, NNODES);
    finalize_kernel<<<1, 128>>>(sums + 0, 1.0f / NNODES, g1, be1, aff + 0);

    // ---- drug layer 2: gemm reads raw agg1 with fused bn-apply ; gather ; stats
    gemm128<<<gGemmN, 256>>>(bufB, W2, nullptr, bufA, NNODES, 128, 0, b1, aff + 0);
    gather_kernel<<<gGather, 256>>>(bufA, bufB);
    bn_stats_kernel<<<2048, 128>>>(bufB, b2, 1, sums + 256, NNODES);
    finalize_kernel<<<1, 128>>>(sums + 256, 1.0f / NNODES, g2, be2, aff + 256);

    // ---- fused bn-apply + global max pool -> out[0 : G*F)
    bounds_kernel<<<gN, T>>>(ibatch);
    segmax_kernel<<<gGF, T>>>(bufB, b2, aff + 256, out);

    // ---- cell branch -> out[G*F : 2*G*F)
    gemm128<<<gGemmG, 256>>>(gexpr, Wc1, bc1, cell, NG, DCELL, 2, nullptr, nullptr);
    bn_stats_kernel<<<512, 128>>>(cell, nullptr, 0, sums + 512, NG);
    bn_apply_kernel<<<gGF, T>>>(cell, sums + 512, gc, bec, cell, NG);
    gemm128<<<gGemmG, 256>>>(cell, Wc2, bc2, out + (size_t)NG * F, NG, 128, 1, nullptr, nullptr);
}

// round 4
// speedup vs baseline: 1.5196x; 1.2469x over previous
#include <cuda_runtime.h>
#include <cuda_bf16.h>
#include <math.h>
#include <cstdint>

#define NNODES 200000
#define NEDGES 800000
#define NG     4096
#define DCELL  954
#define F      128
#define BN_EPS 1e-5f
#define NBLK   782          // ceil(NNODES/256)

// ================= mma.sync helpers (portable sm_80+ tensor path) ===============
__device__ __forceinline__ uint32_t smem_to_u32(const void* p) {
    uint32_t a;
    asm("{ .reg .u64 t; cvta.to.shared.u64 t, %1; cvt.u32.u64 %0, t; }" : "=r"(a) : "l"(p));
    return a;
}

#define LDSM_X4(r, addr) \
    asm volatile("ldmatrix.sync.aligned.m8n8.x4.shared.b16 {%0,%1,%2,%3}, [%4];" \
        : "=r"((r)[0]), "=r"((r)[1]), "=r"((r)[2]), "=r"((r)[3]) : "r"(addr))

#define MMA16816(c, a, b0, b1) \
    asm volatile("mma.sync.aligned.m16n8k16.row.col.f32.bf16.bf16.f32 " \
        "{%0,%1,%2,%3}, {%4,%5,%6,%7}, {%8,%9}, {%0,%1,%2,%3};" \
        : "+f"((c)[0]), "+f"((c)[1]), "+f"((c)[2]), "+f"((c)[3]) \
        : "r"((a)[0]), "r"((a)[1]), "r"((a)[2]), "r"((a)[3]), "r"(b0), "r"(b1))

__device__ __forceinline__ uint32_t packbf2(float x, float y) {
    __nv_bfloat162 t = __halves2bfloat162(__float2bfloat16(x), __float2bfloat16(y));
    return *reinterpret_cast<uint32_t*>(&t);
}

// ================= scratch =======================================================
__device__ float g_bufA[(size_t)NNODES * F];
__device__ float g_bufB[(size_t)NNODES * F];
__device__ float g_dinv[NNODES];
__device__ int   g_deg[NNODES];
__device__ int   g_cursor[NNODES];
__device__ int   g_csr_ptr[NNODES + 1];
__device__ int   g_csr_src[NEDGES];
__device__ int   g_blocksums[1024];
__device__ int   g_blockoff[1024];
__device__ float g_cell[(size_t)NG * F];
__device__ float g_sums[3 * 2 * F];
__device__ float g_aff[2 * 2 * F];
__device__ int   g_start[NG + 1];
__device__ __nv_bfloat16 g_w1hi[F * F], g_w1lo[F * F], g_w2hi[F * F], g_w2lo[F * F];

// ================= init / degree / CSR ==========================================
__global__ void init_kernel() {
    int i = blockIdx.x * blockDim.x + threadIdx.x;
    if (i < NNODES) { g_deg[i] = 0; g_cursor[i] = 0; }
    if (i < 3 * 2 * F) g_sums[i] = 0.0f;
}
__global__ void deg_kernel(const int* __restrict__ dst) {
    int e = blockIdx.x * blockDim.x + threadIdx.x;
    if (e < NEDGES) atomicAdd(&g_deg[dst[e]], 1);
}
__global__ void dinv_kernel() {
    int i = blockIdx.x * blockDim.x + threadIdx.x;
    if (i < NNODES) g_dinv[i] = rsqrtf((float)g_deg[i] + 1.0f);
}
__global__ void scan1_kernel() {
    __shared__ int sh[256];
    int i = blockIdx.x * 256 + threadIdx.x;
    int v = (i < NNODES) ? g_deg[i] : 0;
    sh[threadIdx.x] = v;
    __syncthreads();
#pragma unroll
    for (int off = 1; off < 256; off <<= 1) {
        int t = (threadIdx.x >= off) ? sh[threadIdx.x - off] : 0;
        __syncthreads();
        sh[threadIdx.x] += t;
        __syncthreads();
    }
    if (i < NNODES) g_csr_ptr[i] = sh[threadIdx.x] - v;
    if (threadIdx.x == 255) g_blocksums[blockIdx.x] = sh[255];
}
__global__ void scan2_kernel() {
    __shared__ int sh[1024];
    int t = threadIdx.x;
    int v = (t < NBLK) ? g_blocksums[t] : 0;
    sh[t] = v;
    __syncthreads();
#pragma unroll
    for (int off = 1; off < 1024; off <<= 1) {
        int u = (t >= off) ? sh[t - off] : 0;
        __syncthreads();
        sh[t] += u;
        __syncthreads();
    }
    if (t < NBLK) g_blockoff[t] = sh[t] - v;
}
__global__ void scan3_kernel() {
    int i = blockIdx.x * blockDim.x + threadIdx.x;
    if (i < NNODES) g_csr_ptr[i] += g_blockoff[i >> 8];
    if (i == 0) g_csr_ptr[NNODES] = NEDGES;
}
__global__ void fill_kernel(const int* __restrict__ src, const int* __restrict__ dst) {
    int e = blockIdx.x * blockDim.x + threadIdx.x;
    if (e >= NEDGES) return;
    int d = dst[e];
    int pos = g_csr_ptr[d] + atomicAdd(&g_cursor[d], 1);
    g_csr_src[pos] = src[e];
}

// ================= weight prep: transpose + bf16 split ==========================
// input W[k][n] (k-major) -> Whi/Wlo[n][k]
__global__ void wprep_kernel(const float* __restrict__ W1, const float* __restrict__ W2) {
    int i = blockIdx.x * blockDim.x + threadIdx.x;
    if (i >= F * F) return;
    int k = i >> 7, n = i & 127;
    float v1 = W1[i];
    __nv_bfloat16 h1 = __float2bfloat16(v1);
    g_w1hi[n * F + k] = h1;
    g_w1lo[n * F + k] = __float2bfloat16(v1 - __bfloat162float(h1));
    float v2 = W2[i];
    __nv_bfloat16 h2 = __float2bfloat16(v2);
    g_w2hi[n * F + k] = h2;
    g_w2lo[n * F + k] = __float2bfloat16(v2 - __bfloat162float(h2));
}

// ================= tensor GEMM: C[M,128] = A'[M,128] @ W[128,128] ================
// A' optional: relu(A+prebias[k])*aff[k] + aff[F+k] (fused BN-apply)
// W pre-transposed + split: Whi/Wlo[n*128+k] bf16. 3-term Markidis split.
#define AST    136            // smem row stride in bf16 elems (272 B: 16B-aligned, conflict-free)
#define SA_HI  0
#define SA_LO  34816
#define SW_HI  69632
#define SW_LO  104448
#define MMA_SMEM 139264

__global__ void __launch_bounds__(256, 1)
gemm_mma(const float* __restrict__ A, int M,
         const __nv_bfloat16* __restrict__ Whi, const __nv_bfloat16* __restrict__ Wlo,
         float* __restrict__ C,
         const float* __restrict__ prebias, const float* __restrict__ aff)
{
    extern __shared__ char sm[];
    const int tid  = threadIdx.x;
    const int lane = tid & 31;
    const int wid  = tid >> 5;
    const int m0   = blockIdx.x * 128;

    // ---- W tiles -> smem [n][k], row stride AST
    for (int i = tid; i < 2048; i += 256) {
        int n = i >> 4, kg = i & 15;
        uint4 vh = *(const uint4*)(Whi + n * 128 + kg * 8);
        uint4 vl = *(const uint4*)(Wlo + n * 128 + kg * 8);
        *(uint4*)(sm + SW_HI + ((size_t)n * AST + kg * 8) * 2) = vh;
        *(uint4*)(sm + SW_LO + ((size_t)n * AST + kg * 8) * 2) = vl;
    }

    // ---- A tile -> transform -> bf16 hi/lo smem [m][k]
    {
        int row = tid >> 1;
        int cb  = (tid & 1) * 64;
        int gm  = m0 + row;
        const float4* ar = (gm < M) ? (const float4*)(A + (size_t)gm * 128 + cb) : nullptr;
#pragma unroll
        for (int j = 0; j < 16; j++) {
            float4 v = ar ? ar[j] : make_float4(0.f, 0.f, 0.f, 0.f);
            int k = cb + j * 4;
            if (prebias && ar) {
                v.x = fmaf(fmaxf(v.x + prebias[k + 0], 0.0f), aff[k + 0], aff[F + k + 0]);
                v.y = fmaf(fmaxf(v.y + prebias[k + 1], 0.0f), aff[k + 1], aff[F + k + 1]);
                v.z = fmaf(fmaxf(v.z + prebias[k + 2], 0.0f), aff[k + 2], aff[F + k + 2]);
                v.w = fmaf(fmaxf(v.w + prebias[k + 3], 0.0f), aff[k + 3], aff[F + k + 3]);
            }
            uint32_t h01 = packbf2(v.x, v.y), h23 = packbf2(v.z, v.w);
            float rx = v.x - __bfloat162float(__float2bfloat16(v.x));
            float ry = v.y - __bfloat162float(__float2bfloat16(v.y));
            float rz = v.z - __bfloat162float(__float2bfloat16(v.z));
            float rw = v.w - __bfloat162float(__float2bfloat16(v.w));
            uint32_t l01 = packbf2(rx, ry), l23 = packbf2(rz, rw);
            size_t off = ((size_t)row * AST + k) * 2;
            *(uint2*)(sm + SA_HI + off) = make_uint2(h01, h23);
            *(uint2*)(sm + SA_LO + off) = make_uint2(l01, l23);
        }
    }
    __syncthreads();

    // ---- warp tiling: 4 (M) x 2 (N); each warp 32x64
    const int wm = (wid & 3) * 32;
    const int wn = (wid >> 2) * 64;
    uint32_t sb = smem_to_u32(sm);

    uint32_t aHi = sb + SA_HI + (((uint32_t)(wm + (lane & 15)) * AST + (lane >> 4) * 8) << 1);
    uint32_t aLo = aHi + (SA_LO - SA_HI);
    uint32_t brw = wn + (lane >> 4) * 8 + (lane & 7);
    uint32_t bHi = sb + SW_HI + ((brw * AST + ((lane >> 3) & 1) * 8) << 1);
    uint32_t bLo = bHi + (SW_LO - SW_HI);

    float c[2][8][4];
#pragma unroll
    for (int f = 0; f < 2; f++)
#pragma unroll
        for (int j = 0; j < 8; j++)
#pragma unroll
            for (int e = 0; e < 4; e++) c[f][j][e] = 0.0f;

#pragma unroll
    for (int ks = 0; ks < 8; ks++) {
        const uint32_t ko = ks * 32;                 // 16 bf16 per k-step
        uint32_t ah[2][4], al[2][4], bh[4][4], bl[4][4];
        LDSM_X4(ah[0], aHi + ko);
        LDSM_X4(ah[1], aHi + ko + 16 * AST * 2);
        LDSM_X4(al[0], aLo + ko);
        LDSM_X4(al[1], aLo + ko + 16 * AST * 2);
#pragma unroll
        for (int p = 0; p < 4; p++) {
            LDSM_X4(bh[p], bHi + ko + p * 16 * AST * 2);
            LDSM_X4(bl[p], bLo + ko + p * 16 * AST * 2);
        }
#pragma unroll
        for (int f = 0; f < 2; f++)
#pragma unroll
            for (int j = 0; j < 8; j++) {
                uint32_t b0h = bh[j >> 1][(j & 1) * 2], b1h = bh[j >> 1][(j & 1) * 2 + 1];
                uint32_t b0l = bl[j >> 1][(j & 1) * 2], b1l = bl[j >> 1][(j & 1) * 2 + 1];
                MMA16816(c[f][j], ah[f], b0h, b1h);
                MMA16816(c[f][j], al[f], b0h, b1h);
                MMA16816(c[f][j], ah[f], b0l, b1l);
            }
    }

    // ---- epilogue
    const int r0 = lane >> 2, cc = (lane & 3) * 2;
#pragma unroll
    for (int f = 0; f < 2; f++) {
        int row = m0 + wm + f * 16 + r0;
#pragma unroll
        for (int j = 0; j < 8; j++) {
            int col = wn + j * 8 + cc;
            if (row < M)
                *(float2*)(C + (size_t)row * 128 + col) = make_float2(c[f][j][0], c[f][j][1]);
            if (row + 8 < M)
                *(float2*)(C + (size_t)(row + 8) * 128 + col) = make_float2(c[f][j][2], c[f][j][3]);
        }
    }
}

// ================= gather (CSR, no atomics) + fused BN stats =====================
__global__ void gather_kernel(const float* __restrict__ h, float* __restrict__ agg,
                              const float* __restrict__ bias, float* __restrict__ sums)
{
    __shared__ float ss[256];
    int tid = threadIdx.x;                       // 512 threads = 16 warps = 16 nodes
    if (tid < 256) ss[tid] = 0.0f;
    __syncthreads();

    int node = blockIdx.x * 16 + (tid >> 5);
    int lane = tid & 31;

    if (node < NNODES) {
        int beg = g_csr_ptr[node];
        int end = g_csr_ptr[node + 1];
        float di = g_dinv[node];
        const float4* hv = (const float4*)h;
        float4 acc = hv[(size_t)node * 32 + lane];
        float sn = di * di;
        acc.x *= sn; acc.y *= sn; acc.z *= sn; acc.w *= sn;
        int e = beg;
        for (; e + 1 < end; e += 2) {
            int s0 = __ldg(&g_csr_src[e]);
            int s1 = __ldg(&g_csr_src[e + 1]);
            float n0 = di * g_dinv[s0];
            float n1 = di * g_dinv[s1];
            float4 v0 = hv[(size_t)s0 * 32 + lane];
            float4 v1 = hv[(size_t)s1 * 32 + lane];
            acc.x = fmaf(v0.x, n0, acc.x); acc.y = fmaf(v0.y, n0, acc.y);
            acc.z = fmaf(v0.z, n0, acc.z); acc.w = fmaf(v0.w, n0, acc.w);
            acc.x = fmaf(v1.x, n1, acc.x); acc.y = fmaf(v1.y, n1, acc.y);
            acc.z = fmaf(v1.z, n1, acc.z); acc.w = fmaf(v1.w, n1, acc.w);
        }
        if (e < end) {
            int s0 = __ldg(&g_csr_src[e]);
            float n0 = di * g_dinv[s0];
            float4 v0 = hv[(size_t)s0 * 32 + lane];
            acc.x = fmaf(v0.x, n0, acc.x); acc.y = fmaf(v0.y, n0, acc.y);
            acc.z = fmaf(v0.z, n0, acc.z); acc.w = fmaf(v0.w, n0, acc.w);
        }
        ((float4*)agg)[(size_t)node * 32 + lane] = acc;

        int d = lane * 4;
        float v0 = fmaxf(acc.x + bias[d + 0], 0.0f);
        float v1 = fmaxf(acc.y + bias[d + 1], 0.0f);
        float v2 = fmaxf(acc.z + bias[d + 2], 0.0f);
        float v3 = fmaxf(acc.w + bias[d + 3], 0.0f);
        atomicAdd(&ss[d + 0], v0);  atomicAdd(&ss[128 + d + 0], v0 * v0);
        atomicAdd(&ss[d + 1], v1);  atomicAdd(&ss[128 + d + 1], v1 * v1);
        atomicAdd(&ss[d + 2], v2);  atomicAdd(&ss[128 + d + 2], v2 * v2);
        atomicAdd(&ss[d + 3], v3);  atomicAdd(&ss[128 + d + 3], v3 * v3);
    }
    __syncthreads();
    if (tid < 256) atomicAdd(&sums[tid], ss[tid]);
}

// ================= BN finalize / stats / apply ===================================
__global__ void finalize_kernel(const float* __restrict__ sums, float invM,
                                const float* __restrict__ gamma, const float* __restrict__ beta,
                                float* __restrict__ aff)
{
    int d = threadIdx.x;
    float m = sums[d] * invM;
    float var = sums[F + d] * invM - m * m;
    float r = rsqrtf(var + BN_EPS);
    float sc = gamma[d] * r;
    aff[d]     = sc;
    aff[F + d] = beta[d] - sc * m;
}

__global__ void bn_stats_kernel(const float* __restrict__ in, float* __restrict__ sums, int M) {
    int d = threadIdx.x;
    float s = 0.0f, q = 0.0f;
    for (int r = blockIdx.x; r < M; r += gridDim.x) {
        float v = in[(size_t)r * F + d];
        s += v; q += v * v;
    }
    atomicAdd(&sums[d], s);
    atomicAdd(&sums[F + d], q);
}

__global__ void bn_apply_kernel(const float* __restrict__ in, const float* __restrict__ sums,
                                const float* __restrict__ gamma, const float* __restrict__ beta,
                                float* __restrict__ out, int M)
{
    int i = blockIdx.x * blockDim.x + threadIdx.x;
    if (i >= M * F) return;
    int d = i & 127;
    float invM = 1.0f / (float)M;
    float m   = sums[d] * invM;
    float var = sums[F + d] * invM - m * m;
    out[i] = gamma[d] * (in[i] - m) * rsqrtf(var + BN_EPS) + beta[d];
}

// ================= SIMT GEMM (cell branch only) =================================
__global__ __launch_bounds__(256) void gemm128(
    const float* __restrict__ A, const float* __restrict__ B,
    const float* __restrict__ bias, float* __restrict__ C,
    int M, int K, int act)
{
    __shared__ float As[16][132];
    __shared__ float Bs[16][128];
    const int tid = threadIdx.x;
    const int m0  = blockIdx.x * 128;
    const int tn  = tid & 15;
    const int tm  = tid >> 4;
    float acc[8][8];
#pragma unroll
    for (int i = 0; i < 8; i++)
#pragma unroll
        for (int j = 0; j < 8; j++) acc[i][j] = 0.0f;
    const int arow = tid >> 4, acol = tid & 15;
    const int brow = tid >> 7, bcol = tid & 127;
    for (int kk = 0; kk < K; kk += 16) {
#pragma unroll
        for (int p = 0; p < 8; p++) {
            int m = p * 16 + arow, gk = kk + acol, gm = m0 + m;
            float v = 0.0f;
            if (gm < M && gk < K) v = A[(size_t)gm * K + gk];
            As[acol][m] = v;
        }
#pragma unroll
        for (int q = 0; q < 8; q++) {
            int k = q * 2 + brow, gk = kk + k;
            Bs[k][bcol] = (gk < K) ? B[(size_t)gk * 128 + bcol] : 0.0f;
        }
        __syncthreads();
#pragma unroll
        for (int k = 0; k < 16; k++) {
            float4 a0 = *(const float4*)&As[k][tm * 8];
            float4 a1 = *(const float4*)&As[k][tm * 8 + 4];
            float4 b0 = *(const float4*)&Bs[k][tn * 8];
            float4 b1 = *(const float4*)&Bs[k][tn * 8 + 4];
            float a[8] = {a0.x, a0.y, a0.z, a0.w, a1.x, a1.y, a1.z, a1.w};
            float b[8] = {b0.x, b0.y, b0.z, b0.w, b1.x, b1.y, b1.z, b1.w};
#pragma unroll
            for (int i = 0; i < 8; i++)
#pragma unroll
                for (int j = 0; j < 8; j++)
                    acc[i][j] = fmaf(a[i], b[j], acc[i][j]);
        }
        __syncthreads();
    }
#pragma unroll
    for (int i = 0; i < 8; i++) {
        int gm = m0 + tm * 8 + i;
        if (gm >= M) continue;
        float o[8];
#pragma unroll
        for (int j = 0; j < 8; j++) {
            float v = acc[i][j] + bias[tn * 8 + j];
            if (act == 1)      v = fmaxf(v, 0.0f);
            else if (act == 2) v = tanhf(v);
            o[j] = v;
        }
        float4* cp = (float4*)&C[(size_t)gm * 128 + tn * 8];
        cp[0] = make_float4(o[0], o[1], o[2], o[3]);
        cp[1] = make_float4(o[4], o[5], o[6], o[7]);
    }
}

// ================= segment bounds + fused bn+segmax ==============================
__global__ void bounds_kernel(const int* __restrict__ ib) {
    int i = blockIdx.x * blockDim.x + threadIdx.x;
    if (i >= NNODES) return;
    if (i == 0) { g_start[ib[0]] = 0; g_start[NG] = NNODES; }
    else {
        int g = ib[i];
        if (ib[i - 1] != g) g_start[g] = i;
    }
}

__global__ void segmax_kernel(const float* __restrict__ h, const float* __restrict__ bias,
                              const float* __restrict__ aff, float* __restrict__ out)
{
    int idx = blockIdx.x * blockDim.x + threadIdx.x;
    if (idx >= NG * F) return;
    int g = idx >> 7, d = idx & 127;
    int s = g_start[g], e = g_start[g + 1];
    float b = bias[d], sc = aff[d], sh = aff[F + d];
    float m = -3.402823466e38f;
    for (int r = s; r < e; r++) {
        float v = fmaxf(h[(size_t)r * F + d] + b, 0.0f);
        m = fmaxf(m, fmaf(v, sc, sh));
    }
    out[idx] = m;
}

// ================= launch ========================================================
extern "C" void kernel_launch(void* const* d_in, const int* in_sizes, int n_in,
                              void* d_out, int out_size)
{
    const float* x      = (const float*)d_in[0];
    const int*   eidx   = (const int*)  d_in[1];
    const int*   ibatch = (const int*)  d_in[2];
    const float* gexpr  = (const float*)d_in[3];
    const float* W1  = (const float*)d_in[4];
    const float* b1  = (const float*)d_in[5];
    const float* g1  = (const float*)d_in[6];
    const float* be1 = (const float*)d_in[7];
    const float* W2  = (const float*)d_in[8];
    const float* b2  = (const float*)d_in[9];
    const float* g2  = (const float*)d_in[10];
    const float* be2 = (const float*)d_in[11];
    const float* Wc1 = (const float*)d_in[12];
    const float* bc1 = (const float*)d_in[13];
    const float* gc  = (const float*)d_in[14];
    const float* bec = (const float*)d_in[15];
    const float* Wc2 = (const float*)d_in[16];
    const float* bc2 = (const float*)d_in[17];
    float* out = (float*)d_out;

    const int* src = eidx;
    const int* dst = eidx + NEDGES;

    float* bufA; cudaGetSymbolAddress((void**)&bufA, g_bufA);
    float* bufB; cudaGetSymbolAddress((void**)&bufB, g_bufB);
    float* cell; cudaGetSymbolAddress((void**)&cell, g_cell);
    float* sums; cudaGetSymbolAddress((void**)&sums, g_sums);
    float* aff;  cudaGetSymbolAddress((void**)&aff,  g_aff);
    __nv_bfloat16 *w1hi, *w1lo, *w2hi, *w2lo;
    cudaGetSymbolAddress((void**)&w1hi, g_w1hi);
    cudaGetSymbolAddress((void**)&w1lo, g_w1lo);
    cudaGetSymbolAddress((void**)&w2hi, g_w2hi);
    cudaGetSymbolAddress((void**)&w2lo, g_w2lo);

    cudaFuncSetAttribute(gemm_mma, cudaFuncAttributeMaxDynamicSharedMemorySize, MMA_SMEM);

    const int T = 256;
    int gN  = (NNODES + T - 1) / T;
    int gE  = (NEDGES + T - 1) / T;
    int gGF = (NG * F + T - 1) / T;
    int gGather = (NNODES + 15) / 16;
    int gTile   = (NNODES + 127) / 128;
    int gGemmG  = (NG + 127) / 128;

    // degrees + CSR + weight prep
    init_kernel<<<gN, T>>>();
    deg_kernel<<<gE, T>>>(dst);
    dinv_kernel<<<gN, T>>>();
    scan1_kernel<<<NBLK, 256>>>();
    scan2_kernel<<<1, 1024>>>();
    scan3_kernel<<<gN, T>>>();
    fill_kernel<<<gE, T>>>(src, dst);
    wprep_kernel<<<(F * F + 255) / 256, 256>>>(W1, W2);

    // ---- drug layer 1
    gemm_mma<<<gTile, 256, MMA_SMEM>>>(x, NNODES, w1hi, w1lo, bufA, nullptr, nullptr);
    gather_kernel<<<gGather, 512>>>(bufA, bufB, b1, sums + 0);
    finalize_kernel<<<1, 128>>>(sums + 0, 1.0f / NNODES, g1, be1, aff + 0);

    // ---- drug layer 2 (layer-1 BN-apply fused into A-load)
    gemm_mma<<<gTile, 256, MMA_SMEM>>>(bufB, NNODES, w2hi, w2lo, bufA, b1, aff + 0);
    gather_kernel<<<gGather, 512>>>(bufA, bufB, b2, sums + 256);
    finalize_kernel<<<1, 128>>>(sums + 256, 1.0f / NNODES, g2, be2, aff + 256);

    // ---- fused bn-apply + global max pool
    bounds_kernel<<<gN, T>>>(ibatch);
    segmax_kernel<<<gGF, T>>>(bufB, b2, aff + 256, out);

    // ---- cell branch
    gemm128<<<gGemmG, 256>>>(gexpr, Wc1, bc1, cell, NG, DCELL, 2);
    bn_stats_kernel<<<512, 128>>>(cell, sums + 512, NG);
    bn_apply_kernel<<<gGF, T>>>(cell, sums + 512, gc, bec, cell, NG);
    gemm128<<<gGemmG, 256>>>(cell, Wc2, bc2, out + (size_t)NG * F, NG, 128, 1);
}

// round 5
// speedup vs baseline: 2.3874x; 1.5711x over previous
#include <cuda_runtime.h>
#include <cuda_bf16.h>
#include <math.h>
#include <cstdint>

#define NNODES 200000
#define NEDGES 800000
#define NG     4096
#define DCELL  954
#define F      128
#define BN_EPS 1e-5f
#define NBLK   782          // ceil(NNODES/256)

// ================= mma.sync helpers (portable sm_80+ tensor path) ===============
__device__ __forceinline__ uint32_t smem_to_u32(const void* p) {
    uint32_t a;
    asm("{ .reg .u64 t; cvta.to.shared.u64 t, %1; cvt.u32.u64 %0, t; }" : "=r"(a) : "l"(p));
    return a;
}

#define LDSM_X4(r, addr) \
    asm volatile("ldmatrix.sync.aligned.m8n8.x4.shared.b16 {%0,%1,%2,%3}, [%4];" \
        : "=r"((r)[0]), "=r"((r)[1]), "=r"((r)[2]), "=r"((r)[3]) : "r"(addr))

#define MMA16816(c, a, b0, b1) \
    asm volatile("mma.sync.aligned.m16n8k16.row.col.f32.bf16.bf16.f32 " \
        "{%0,%1,%2,%3}, {%4,%5,%6,%7}, {%8,%9}, {%0,%1,%2,%3};" \
        : "+f"((c)[0]), "+f"((c)[1]), "+f"((c)[2]), "+f"((c)[3]) \
        : "r"((a)[0]), "r"((a)[1]), "r"((a)[2]), "r"((a)[3]), "r"(b0), "r"(b1))

// split (x,y) into hi bf16x2 + residual-lo bf16x2 (Markidis)
__device__ __forceinline__ void splitpack(float x, float y, uint32_t& hi, uint32_t& lo) {
    __nv_bfloat16 hx = __float2bfloat16(x), hy = __float2bfloat16(y);
    __nv_bfloat162 h2 = __halves2bfloat162(hx, hy);
    hi = *reinterpret_cast<uint32_t*>(&h2);
    __nv_bfloat162 l2 = __halves2bfloat162(__float2bfloat16(x - __bfloat162float(hx)),
                                           __float2bfloat16(y - __bfloat162float(hy)));
    lo = *reinterpret_cast<uint32_t*>(&l2);
}

// ================= scratch =======================================================
__device__ float g_bufA[(size_t)NNODES * F];
__device__ float g_bufB[(size_t)NNODES * F];
__device__ float g_dinv[NNODES];
__device__ int   g_deg[NNODES];
__device__ int   g_cursor[NNODES];
__device__ int   g_csr_ptr[NNODES + 1];
__device__ int   g_csr_src[NEDGES];
__device__ int   g_blocksums[1024];
__device__ int   g_blockoff[1024];
__device__ float g_cell[(size_t)NG * F];
__device__ float g_sums[3 * 2 * F];
__device__ float g_aff[2 * 2 * F];
__device__ int   g_start[NG + 1];
__device__ __nv_bfloat16 g_w1hi[F * F], g_w1lo[F * F], g_w2hi[F * F], g_w2lo[F * F];

// ================= init / degree / CSR ==========================================
__global__ void init_kernel() {
    int i = blockIdx.x * blockDim.x + threadIdx.x;
    if (i < NNODES) { g_deg[i] = 0; g_cursor[i] = 0; }
    if (i < 2 * 2 * F) g_sums[i] = 0.0f;           // drug-layer sums (cell zeroed on its stream)
}
__global__ void zero_cell_sums() {
    int i = threadIdx.x;
    g_sums[512 + i] = 0.0f;
}
__global__ void deg_kernel(const int* __restrict__ dst) {
    int e = blockIdx.x * blockDim.x + threadIdx.x;
    if (e < NEDGES) atomicAdd(&g_deg[dst[e]], 1);
}
__global__ void dinv_kernel() {
    int i = blockIdx.x * blockDim.x + threadIdx.x;
    if (i < NNODES) g_dinv[i] = rsqrtf((float)g_deg[i] + 1.0f);
}
__global__ void scan1_kernel() {
    __shared__ int sh[256];
    int i = blockIdx.x * 256 + threadIdx.x;
    int v = (i < NNODES) ? g_deg[i] : 0;
    sh[threadIdx.x] = v;
    __syncthreads();
#pragma unroll
    for (int off = 1; off < 256; off <<= 1) {
        int t = (threadIdx.x >= off) ? sh[threadIdx.x - off] : 0;
        __syncthreads();
        sh[threadIdx.x] += t;
        __syncthreads();
    }
    if (i < NNODES) g_csr_ptr[i] = sh[threadIdx.x] - v;
    if (threadIdx.x == 255) g_blocksums[blockIdx.x] = sh[255];
}
__global__ void scan2_kernel() {
    __shared__ int sh[1024];
    int t = threadIdx.x;
    int v = (t < NBLK) ? g_blocksums[t] : 0;
    sh[t] = v;
    __syncthreads();
#pragma unroll
    for (int off = 1; off < 1024; off <<= 1) {
        int u = (t >= off) ? sh[t - off] : 0;
        __syncthreads();
        sh[t] += u;
        __syncthreads();
    }
    if (t < NBLK) g_blockoff[t] = sh[t] - v;
}
__global__ void scan3_kernel() {
    int i = blockIdx.x * blockDim.x + threadIdx.x;
    if (i < NNODES) g_csr_ptr[i] += g_blockoff[i >> 8];
    if (i == 0) g_csr_ptr[NNODES] = NEDGES;
}
__global__ void fill_kernel(const int* __restrict__ src, const int* __restrict__ dst) {
    int e = blockIdx.x * blockDim.x + threadIdx.x;
    if (e >= NEDGES) return;
    int d = dst[e];
    int pos = g_csr_ptr[d] + atomicAdd(&g_cursor[d], 1);
    g_csr_src[pos] = src[e];
}

// ================= weight prep: transpose + bf16 split ==========================
__global__ void wprep_kernel(const float* __restrict__ W1, const float* __restrict__ W2) {
    int i = blockIdx.x * blockDim.x + threadIdx.x;
    if (i >= F * F) return;
    int k = i >> 7, n = i & 127;
    float v1 = W1[i];
    __nv_bfloat16 h1 = __float2bfloat16(v1);
    g_w1hi[n * F + k] = h1;
    g_w1lo[n * F + k] = __float2bfloat16(v1 - __bfloat162float(h1));
    float v2 = W2[i];
    __nv_bfloat16 h2 = __float2bfloat16(v2);
    g_w2hi[n * F + k] = h2;
    g_w2lo[n * F + k] = __float2bfloat16(v2 - __bfloat162float(h2));
}

// ================= tensor GEMM: C[M,128] = A'[M,128] @ W[128,128] ================
// A fragments loaded DIRECTLY from global (fp32) -> split in regs. W hi/lo in smem.
#define AST    136
#define SW_HI  0
#define SW_LO  (128 * AST * 2)         // 34816
#define MMA_SMEM (2 * 128 * AST * 2)   // 69632

__global__ void __launch_bounds__(256, 2)
gemm_mma(const float* __restrict__ A, int M,
         const __nv_bfloat16* __restrict__ Whi, const __nv_bfloat16* __restrict__ Wlo,
         float* __restrict__ C,
         const float* __restrict__ prebias, const float* __restrict__ aff)
{
    extern __shared__ char sm[];
    const int tid  = threadIdx.x;
    const int lane = tid & 31;
    const int wid  = tid >> 5;
    const int m0   = blockIdx.x * 128;

    // ---- W tiles -> smem [n][k], row stride AST
    for (int i = tid; i < 2048; i += 256) {
        int n = i >> 4, kg = i & 15;
        *(uint4*)(sm + SW_HI + ((size_t)n * AST + kg * 8) * 2) = *(const uint4*)(Whi + n * 128 + kg * 8);
        *(uint4*)(sm + SW_LO + ((size_t)n * AST + kg * 8) * 2) = *(const uint4*)(Wlo + n * 128 + kg * 8);
    }
    __syncthreads();

    // warp tiling: 4 (M) x 2 (N); each warp 32 rows x 64 cols
    const int wm = (wid & 3) * 32;
    const int wn = (wid >> 2) * 64;
    uint32_t sb  = smem_to_u32(sm);
    uint32_t brw = wn + (lane >> 4) * 8 + (lane & 7);
    uint32_t bHi = sb + SW_HI + ((brw * AST + ((lane >> 3) & 1) * 8) << 1);
    uint32_t bLo = bHi + SW_LO;

    const int r0 = lane >> 2;
    const int c0 = (lane & 3) * 2;
    const int rowA = m0 + wm + r0;

    float c[2][8][4];
#pragma unroll
    for (int f = 0; f < 2; f++)
#pragma unroll
        for (int j = 0; j < 8; j++)
#pragma unroll
            for (int e = 0; e < 4; e++) c[f][j][e] = 0.0f;

#pragma unroll
    for (int ks = 0; ks < 8; ks++) {
        const int kc = ks * 16 + c0;

        // per-k BN-apply constants (cols kc, kc+1, kc+8, kc+9)
        float2 pa, pb, sa_, sb_, ha, hb;
        if (prebias) {
            pa = *(const float2*)(prebias + kc);      pb = *(const float2*)(prebias + kc + 8);
            sa_ = *(const float2*)(aff + kc);         sb_ = *(const float2*)(aff + kc + 8);
            ha = *(const float2*)(aff + F + kc);      hb = *(const float2*)(aff + F + kc + 8);
        }

        // ---- A fragments direct from global, split hi/lo in regs
        uint32_t ah[2][4], al[2][4];
#pragma unroll
        for (int f = 0; f < 2; f++) {
            int r = rowA + f * 16;
            bool ok0 = (r < M), ok1 = (r + 8 < M);
            const float* p0 = A + (size_t)r * 128 + kc;
            float2 v00 = ok0 ? *(const float2*)p0            : make_float2(0.f, 0.f);
            float2 v01 = ok0 ? *(const float2*)(p0 + 8)      : make_float2(0.f, 0.f);
            float2 v10 = ok1 ? *(const float2*)(p0 + 1024)   : make_float2(0.f, 0.f);  // +8 rows
            float2 v11 = ok1 ? *(const float2*)(p0 + 1032)   : make_float2(0.f, 0.f);
            if (prebias) {
                v00.x = fmaf(fmaxf(v00.x + pa.x, 0.f), sa_.x, ha.x);
                v00.y = fmaf(fmaxf(v00.y + pa.y, 0.f), sa_.y, ha.y);
                v10.x = fmaf(fmaxf(v10.x + pa.x, 0.f), sa_.x, ha.x);
                v10.y = fmaf(fmaxf(v10.y + pa.y, 0.f), sa_.y, ha.y);
                v01.x = fmaf(fmaxf(v01.x + pb.x, 0.f), sb_.x, hb.x);
                v01.y = fmaf(fmaxf(v01.y + pb.y, 0.f), sb_.y, hb.y);
                v11.x = fmaf(fmaxf(v11.x + pb.x, 0.f), sb_.x, hb.x);
                v11.y = fmaf(fmaxf(v11.y + pb.y, 0.f), sb_.y, hb.y);
            }
            splitpack(v00.x, v00.y, ah[f][0], al[f][0]);
            splitpack(v10.x, v10.y, ah[f][1], al[f][1]);
            splitpack(v01.x, v01.y, ah[f][2], al[f][2]);
            splitpack(v11.x, v11.y, ah[f][3], al[f][3]);
        }

        // ---- B fragments per 16-col group, MMAs interleaved (keeps regs low)
#pragma unroll
        for (int p = 0; p < 4; p++) {
            uint32_t bh[4], bl[4];
            LDSM_X4(bh, bHi + ks * 32 + p * 16 * AST * 2);
            LDSM_X4(bl, bLo + ks * 32 + p * 16 * AST * 2);
#pragma unroll
            for (int f = 0; f < 2; f++)
#pragma unroll
                for (int q = 0; q < 2; q++) {
                    int j = p * 2 + q;
                    MMA16816(c[f][j], ah[f], bh[q * 2], bh[q * 2 + 1]);
                    MMA16816(c[f][j], al[f], bh[q * 2], bh[q * 2 + 1]);
                    MMA16816(c[f][j], ah[f], bl[q * 2], bl[q * 2 + 1]);
                }
        }
    }

    // ---- epilogue
    const int cc = (lane & 3) * 2;
#pragma unroll
    for (int f = 0; f < 2; f++) {
        int row = m0 + wm + f * 16 + r0;
#pragma unroll
        for (int j = 0; j < 8; j++) {
            int col = wn + j * 8 + cc;
            if (row < M)
                *(float2*)(C + (size_t)row * 128 + col) = make_float2(c[f][j][0], c[f][j][1]);
            if (row + 8 < M)
                *(float2*)(C + (size_t)(row + 8) * 128 + col) = make_float2(c[f][j][2], c[f][j][3]);
        }
    }
}

// ================= gather (CSR, no atomics) + fused BN stats =====================
__global__ void gather_kernel(const float* __restrict__ h, float* __restrict__ agg,
                              const float* __restrict__ bias, float* __restrict__ sums)
{
    __shared__ float ss[256];
    int tid = threadIdx.x;                       // 512 threads = 16 warps = 16 nodes
    if (tid < 256) ss[tid] = 0.0f;
    __syncthreads();

    int node = blockIdx.x * 16 + (tid >> 5);
    int lane = tid & 31;

    if (node < NNODES) {
        int beg = g_csr_ptr[node];
        int end = g_csr_ptr[node + 1];
        float di = g_dinv[node];
        const float4* hv = (const float4*)h;
        float4 acc = hv[(size_t)node * 32 + lane];
        float sn = di * di;
        acc.x *= sn; acc.y *= sn; acc.z *= sn; acc.w *= sn;
        int e = beg;
        for (; e + 1 < end; e += 2) {
            int s0 = __ldg(&g_csr_src[e]);
            int s1 = __ldg(&g_csr_src[e + 1]);
            float n0 = di * g_dinv[s0];
            float n1 = di * g_dinv[s1];
            float4 v0 = hv[(size_t)s0 * 32 + lane];
            float4 v1 = hv[(size_t)s1 * 32 + lane];
            acc.x = fmaf(v0.x, n0, acc.x); acc.y = fmaf(v0.y, n0, acc.y);
            acc.z = fmaf(v0.z, n0, acc.z); acc.w = fmaf(v0.w, n0, acc.w);
            acc.x = fmaf(v1.x, n1, acc.x); acc.y = fmaf(v1.y, n1, acc.y);
            acc.z = fmaf(v1.z, n1, acc.z); acc.w = fmaf(v1.w, n1, acc.w);
        }
        if (e < end) {
            int s0 = __ldg(&g_csr_src[e]);
            float n0 = di * g_dinv[s0];
            float4 v0 = hv[(size_t)s0 * 32 + lane];
            acc.x = fmaf(v0.x, n0, acc.x); acc.y = fmaf(v0.y, n0, acc.y);
            acc.z = fmaf(v0.z, n0, acc.z); acc.w = fmaf(v0.w, n0, acc.w);
        }
        ((float4*)agg)[(size_t)node * 32 + lane] = acc;

        int d = lane * 4;
        float v0 = fmaxf(acc.x + bias[d + 0], 0.0f);
        float v1 = fmaxf(acc.y + bias[d + 1], 0.0f);
        float v2 = fmaxf(acc.z + bias[d + 2], 0.0f);
        float v3 = fmaxf(acc.w + bias[d + 3], 0.0f);
        atomicAdd(&ss[d + 0], v0);  atomicAdd(&ss[128 + d + 0], v0 * v0);
        atomicAdd(&ss[d + 1], v1);  atomicAdd(&ss[128 + d + 1], v1 * v1);
        atomicAdd(&ss[d + 2], v2);  atomicAdd(&ss[128 + d + 2], v2 * v2);
        atomicAdd(&ss[d + 3], v3);  atomicAdd(&ss[128 + d + 3], v3 * v3);
    }
    __syncthreads();
    if (tid < 256) atomicAdd(&sums[tid], ss[tid]);
}

// ================= BN finalize / stats / apply ===================================
__global__ void finalize_kernel(const float* __restrict__ sums, float invM,
                                const float* __restrict__ gamma, const float* __restrict__ beta,
                                float* __restrict__ aff)
{
    int d = threadIdx.x;
    float m = sums[d] * invM;
    float var = sums[F + d] * invM - m * m;
    float r = rsqrtf(var + BN_EPS);
    float sc = gamma[d] * r;
    aff[d]     = sc;
    aff[F + d] = beta[d] - sc * m;
}

__global__ void bn_stats_kernel(const float* __restrict__ in, float* __restrict__ sums, int M) {
    int d = threadIdx.x;
    float s = 0.0f, q = 0.0f;
    for (int r = blockIdx.x; r < M; r += gridDim.x) {
        float v = in[(size_t)r * F + d];
        s += v; q += v * v;
    }
    atomicAdd(&sums[d], s);
    atomicAdd(&sums[F + d], q);
}

__global__ void bn_apply_kernel(const float* __restrict__ in, const float* __restrict__ sums,
                                const float* __restrict__ gamma, const float* __restrict__ beta,
                                float* __restrict__ out, int M)
{
    int i = blockIdx.x * blockDim.x + threadIdx.x;
    if (i >= M * F) return;
    int d = i & 127;
    float invM = 1.0f / (float)M;
    float m   = sums[d] * invM;
    float var = sums[F + d] * invM - m * m;
    out[i] = gamma[d] * (in[i] - m) * rsqrtf(var + BN_EPS) + beta[d];
}

// ================= SIMT GEMM (cell branch only) =================================
__global__ __launch_bounds__(256) void gemm128(
    const float* __restrict__ A, const float* __restrict__ B,
    const float* __restrict__ bias, float* __restrict__ C,
    int M, int K, int act)
{
    __shared__ float As[16][132];
    __shared__ float Bs[16][128];
    const int tid = threadIdx.x;
    const int m0  = blockIdx.x * 128;
    const int tn  = tid & 15;
    const int tm  = tid >> 4;
    float acc[8][8];
#pragma unroll
    for (int i = 0; i < 8; i++)
#pragma unroll
        for (int j = 0; j < 8; j++) acc[i][j] = 0.0f;
    const int arow = tid >> 4, acol = tid & 15;
    const int brow = tid >> 7, bcol = tid & 127;
    for (int kk = 0; kk < K; kk += 16) {
#pragma unroll
        for (int p = 0; p < 8; p++) {
            int m = p * 16 + arow, gk = kk + acol, gm = m0 + m;
            float v = 0.0f;
            if (gm < M && gk < K) v = A[(size_t)gm * K + gk];
            As[acol][m] = v;
        }
#pragma unroll
        for (int q = 0; q < 8; q++) {
            int k = q * 2 + brow, gk = kk + k;
            Bs[k][bcol] = (gk < K) ? B[(size_t)gk * 128 + bcol] : 0.0f;
        }
        __syncthreads();
#pragma unroll
        for (int k = 0; k < 16; k++) {
            float4 a0 = *(const float4*)&As[k][tm * 8];
            float4 a1 = *(const float4*)&As[k][tm * 8 + 4];
            float4 b0 = *(const float4*)&Bs[k][tn * 8];
            float4 b1 = *(const float4*)&Bs[k][tn * 8 + 4];
            float a[8] = {a0.x, a0.y, a0.z, a0.w, a1.x, a1.y, a1.z, a1.w};
            float b[8] = {b0.x, b0.y, b0.z, b0.w, b1.x, b1.y, b1.z, b1.w};
#pragma unroll
            for (int i = 0; i < 8; i++)
#pragma unroll
                for (int j = 0; j < 8; j++)
                    acc[i][j] = fmaf(a[i], b[j], acc[i][j]);
        }
        __syncthreads();
    }
#pragma unroll
    for (int i = 0; i < 8; i++) {
        int gm = m0 + tm * 8 + i;
        if (gm >= M) continue;
        float o[8];
#pragma unroll
        for (int j = 0; j < 8; j++) {
            float v = acc[i][j] + bias[tn * 8 + j];
            if (act == 1)      v = fmaxf(v, 0.0f);
            else if (act == 2) v = tanhf(v);
            o[j] = v;
        }
        float4* cp = (float4*)&C[(size_t)gm * 128 + tn * 8];
        cp[0] = make_float4(o[0], o[1], o[2], o[3]);
        cp[1] = make_float4(o[4], o[5], o[6], o[7]);
    }
}

// ================= segment bounds + fused bn+segmax ==============================
__global__ void bounds_kernel(const int* __restrict__ ib) {
    int i = blockIdx.x * blockDim.x + threadIdx.x;
    if (i >= NNODES) return;
    if (i == 0) { g_start[ib[0]] = 0; g_start[NG] = NNODES; }
    else {
        int g = ib[i];
        if (ib[i - 1] != g) g_start[g] = i;
    }
}

__global__ void segmax_kernel(const float* __restrict__ h, const float* __restrict__ bias,
                              const float* __restrict__ aff, float* __restrict__ out)
{
    int idx = blockIdx.x * blockDim.x + threadIdx.x;
    if (idx >= NG * F) return;
    int g = idx >> 7, d = idx & 127;
    int s = g_start[g], e = g_start[g + 1];
    float b = bias[d], sc = aff[d], sh = aff[F + d];
    float m = -3.402823466e38f;
    for (int r = s; r < e; r++) {
        float v = fmaxf(h[(size_t)r * F + d] + b, 0.0f);
        m = fmaxf(m, fmaf(v, sc, sh));
    }
    out[idx] = m;
}

// ================= launch ========================================================
extern "C" void kernel_launch(void* const* d_in, const int* in_sizes, int n_in,
                              void* d_out, int out_size)
{
    const float* x      = (const float*)d_in[0];
    const int*   eidx   = (const int*)  d_in[1];
    const int*   ibatch = (const int*)  d_in[2];
    const float* gexpr  = (const float*)d_in[3];
    const float* W1  = (const float*)d_in[4];
    const float* b1  = (const float*)d_in[5];
    const float* g1  = (const float*)d_in[6];
    const float* be1 = (const float*)d_in[7];
    const float* W2  = (const float*)d_in[8];
    const float* b2  = (const float*)d_in[9];
    const float* g2  = (const float*)d_in[10];
    const float* be2 = (const float*)d_in[11];
    const float* Wc1 = (const float*)d_in[12];
    const float* bc1 = (const float*)d_in[13];
    const float* gc  = (const float*)d_in[14];
    const float* bec = (const float*)d_in[15];
    const float* Wc2 = (const float*)d_in[16];
    const float* bc2 = (const float*)d_in[17];
    float* out = (float*)d_out;

    const int* src = eidx;
    const int* dst = eidx + NEDGES;

    float* bufA; cudaGetSymbolAddress((void**)&bufA, g_bufA);
    float* bufB; cudaGetSymbolAddress((void**)&bufB, g_bufB);
    float* cell; cudaGetSymbolAddress((void**)&cell, g_cell);
    float* sums; cudaGetSymbolAddress((void**)&sums, g_sums);
    float* aff;  cudaGetSymbolAddress((void**)&aff,  g_aff);
    __nv_bfloat16 *w1hi, *w1lo, *w2hi, *w2lo;
    cudaGetSymbolAddress((void**)&w1hi, g_w1hi);
    cudaGetSymbolAddress((void**)&w1lo, g_w1lo);
    cudaGetSymbolAddress((void**)&w2hi, g_w2hi);
    cudaGetSymbolAddress((void**)&w2lo, g_w2lo);

    cudaFuncSetAttribute(gemm_mma, cudaFuncAttributeMaxDynamicSharedMemorySize, MMA_SMEM);

    // side streams + events (created once, on the un-captured correctness call;
    // every call enqueues the identical work DAG)
    static cudaStream_t s_csr = nullptr, s_cell = nullptr;
    static cudaEvent_t ev_root = nullptr, ev_csr = nullptr, ev_cell = nullptr;
    if (!s_csr) {
        cudaStreamCreateWithFlags(&s_csr,  cudaStreamNonBlocking);
        cudaStreamCreateWithFlags(&s_cell, cudaStreamNonBlocking);
        cudaEventCreateWithFlags(&ev_root, cudaEventDisableTiming);
        cudaEventCreateWithFlags(&ev_csr,  cudaEventDisableTiming);
        cudaEventCreateWithFlags(&ev_cell, cudaEventDisableTiming);
    }

    const int T = 256;
    int gN  = (NNODES + T - 1) / T;
    int gE  = (NEDGES + T - 1) / T;
    int gGF = (NG * F + T - 1) / T;
    int gGather = (NNODES + 15) / 16;
    int gTile   = (NNODES + 127) / 128;
    int gGemmG  = (NG + 127) / 128;

    // ---- fork
    cudaEventRecord(ev_root, 0);
    cudaStreamWaitEvent(s_csr,  ev_root, 0);
    cudaStreamWaitEvent(s_cell, ev_root, 0);

    // ---- CSR branch (s_csr): degrees, dinv, scan, fill, bounds
    init_kernel<<<gN, T, 0, s_csr>>>();
    deg_kernel<<<gE, T, 0, s_csr>>>(dst);
    dinv_kernel<<<gN, T, 0, s_csr>>>();
    scan1_kernel<<<NBLK, 256, 0, s_csr>>>();
    scan2_kernel<<<1, 1024, 0, s_csr>>>();
    scan3_kernel<<<gN, T, 0, s_csr>>>();
    fill_kernel<<<gE, T, 0, s_csr>>>(src, dst);
    bounds_kernel<<<gN, T, 0, s_csr>>>(ibatch);
    cudaEventRecord(ev_csr, s_csr);

    // ---- cell branch (s_cell): fully independent, writes out[G*F:2*G*F)
    zero_cell_sums<<<1, 256, 0, s_cell>>>();
    gemm128<<<gGemmG, 256, 0, s_cell>>>(gexpr, Wc1, bc1, cell, NG, DCELL, 2);
    bn_stats_kernel<<<512, 128, 0, s_cell>>>(cell, sums + 512, NG);
    bn_apply_kernel<<<gGF, T, 0, s_cell>>>(cell, sums + 512, gc, bec, cell, NG);
    gemm128<<<gGemmG, 256, 0, s_cell>>>(cell, Wc2, bc2, out + (size_t)NG * F, NG, 128, 1);
    cudaEventRecord(ev_cell, s_cell);

    // ---- main stream: weight prep + GEMM-1 overlap the CSR build
    wprep_kernel<<<(F * F + 255) / 256, 256>>>(W1, W2);
    gemm_mma<<<gTile, 256, MMA_SMEM>>>(x, NNODES, w1hi, w1lo, bufA, nullptr, nullptr);

    cudaStreamWaitEvent(0, ev_csr, 0);

    // ---- drug layer 1 aggregation + BN
    gather_kernel<<<gGather, 512>>>(bufA, bufB, b1, sums + 0);
    finalize_kernel<<<1, 128>>>(sums + 0, 1.0f / NNODES, g1, be1, aff + 0);

    // ---- drug layer 2 (layer-1 BN-apply fused into A fragment load)
    gemm_mma<<<gTile, 256, MMA_SMEM>>>(bufB, NNODES, w2hi, w2lo, bufA, b1, aff + 0);
    gather_kernel<<<gGather, 512>>>(bufA, bufB, b2, sums + 256);
    finalize_kernel<<<1, 128>>>(sums + 256, 1.0f / NNODES, g2, be2, aff + 256);

    // ---- fused bn-apply + global max pool -> out[0:G*F)
    segmax_kernel<<<gGF, T>>>(bufB, b2, aff + 256, out);

    // ---- join cell branch
    cudaStreamWaitEvent(0, ev_cell, 0);
}

// round 6
// speedup vs baseline: 2.4174x; 1.0125x over previous
#include <cuda_runtime.h>
#include <cuda_bf16.h>
#include <math.h>
#include <cstdint>

#define NNODES 200000
#define NEDGES 800000
#define NG     4096
#define DCELL  954
#define F      128
#define BN_EPS 1e-5f
#define NBLK   782          // ceil(NNODES/256)

// ================= mma.sync helpers (portable sm_80+ tensor path) ===============
__device__ __forceinline__ uint32_t smem_to_u32(const void* p) {
    uint32_t a;
    asm("{ .reg .u64 t; cvta.to.shared.u64 t, %1; cvt.u32.u64 %0, t; }" : "=r"(a) : "l"(p));
    return a;
}

#define LDSM_X4(r, addr) \
    asm volatile("ldmatrix.sync.aligned.m8n8.x4.shared.b16 {%0,%1,%2,%3}, [%4];" \
        : "=r"((r)[0]), "=r"((r)[1]), "=r"((r)[2]), "=r"((r)[3]) : "r"(addr))

#define MMA16816(c, a, b0, b1) \
    asm volatile("mma.sync.aligned.m16n8k16.row.col.f32.bf16.bf16.f32 " \
        "{%0,%1,%2,%3}, {%4,%5,%6,%7}, {%8,%9}, {%0,%1,%2,%3};" \
        : "+f"((c)[0]), "+f"((c)[1]), "+f"((c)[2]), "+f"((c)[3]) \
        : "r"((a)[0]), "r"((a)[1]), "r"((a)[2]), "r"((a)[3]), "r"(b0), "r"(b1))

__device__ __forceinline__ void splitpack(float x, float y, uint32_t& hi, uint32_t& lo) {
    __nv_bfloat16 hx = __float2bfloat16(x), hy = __float2bfloat16(y);
    __nv_bfloat162 h2 = __halves2bfloat162(hx, hy);
    hi = *reinterpret_cast<uint32_t*>(&h2);
    __nv_bfloat162 l2 = __halves2bfloat162(__float2bfloat16(x - __bfloat162float(hx)),
                                           __float2bfloat16(y - __bfloat162float(hy)));
    lo = *reinterpret_cast<uint32_t*>(&l2);
}

// ================= scratch =======================================================
__device__ float g_bufA[(size_t)NNODES * F];
__device__ float g_bufB[(size_t)NNODES * F];
__device__ float g_dinv[NNODES];
__device__ int   g_deg[NNODES];
__device__ int   g_cursor[NNODES];
__device__ int   g_csr_ptr[NNODES + 1];
__device__ int   g_csr_src[NEDGES];
__device__ int   g_blocksums[1024];
__device__ int   g_blockoff[1024];
__device__ float g_cell[(size_t)NG * F];
__device__ float g_sums[3 * 2 * F];
__device__ float g_aff[2 * 2 * F];
__device__ int   g_start[NG + 1];
__device__ __nv_bfloat16 g_w1hi[F * F], g_w1lo[F * F], g_w2hi[F * F], g_w2lo[F * F];

// ================= init / degree / CSR ==========================================
__global__ void init_kernel() {
    int i = blockIdx.x * blockDim.x + threadIdx.x;
    if (i < NNODES) { g_deg[i] = 0; g_cursor[i] = 0; }
    if (i < 2 * 2 * F) g_sums[i] = 0.0f;
}
__global__ void zero_cell_sums() {
    g_sums[512 + threadIdx.x] = 0.0f;
}
__global__ void deg_kernel(const int* __restrict__ dst) {
    int e = blockIdx.x * blockDim.x + threadIdx.x;
    if (e < NEDGES) atomicAdd(&g_deg[dst[e]], 1);
}
__global__ void dinv_kernel() {
    int i = blockIdx.x * blockDim.x + threadIdx.x;
    if (i < NNODES) g_dinv[i] = rsqrtf((float)g_deg[i] + 1.0f);
}
__global__ void scan1_kernel() {
    __shared__ int sh[256];
    int i = blockIdx.x * 256 + threadIdx.x;
    int v = (i < NNODES) ? g_deg[i] : 0;
    sh[threadIdx.x] = v;
    __syncthreads();
#pragma unroll
    for (int off = 1; off < 256; off <<= 1) {
        int t = (threadIdx.x >= off) ? sh[threadIdx.x - off] : 0;
        __syncthreads();
        sh[threadIdx.x] += t;
        __syncthreads();
    }
    if (i < NNODES) g_csr_ptr[i] = sh[threadIdx.x] - v;
    if (threadIdx.x == 255) g_blocksums[blockIdx.x] = sh[255];
}
__global__ void scan2_kernel() {
    __shared__ int sh[1024];
    int t = threadIdx.x;
    int v = (t < NBLK) ? g_blocksums[t] : 0;
    sh[t] = v;
    __syncthreads();
#pragma unroll
    for (int off = 1; off < 1024; off <<= 1) {
        int u = (t >= off) ? sh[t - off] : 0;
        __syncthreads();
        sh[t] += u;
        __syncthreads();
    }
    if (t < NBLK) g_blockoff[t] = sh[t] - v;
}
__global__ void scan3_kernel() {
    int i = blockIdx.x * blockDim.x + threadIdx.x;
    if (i < NNODES) g_csr_ptr[i] += g_blockoff[i >> 8];
    if (i == 0) g_csr_ptr[NNODES] = NEDGES;
}
__global__ void fill_kernel(const int* __restrict__ src, const int* __restrict__ dst) {
    int e = blockIdx.x * blockDim.x + threadIdx.x;
    if (e >= NEDGES) return;
    int d = dst[e];
    int pos = g_csr_ptr[d] + atomicAdd(&g_cursor[d], 1);
    g_csr_src[pos] = src[e];
}

// ================= weight prep: transpose + bf16 split ==========================
__global__ void wprep_kernel(const float* __restrict__ W1, const float* __restrict__ W2) {
    int i = blockIdx.x * blockDim.x + threadIdx.x;
    if (i >= F * F) return;
    int k = i >> 7, n = i & 127;
    float v1 = W1[i];
    __nv_bfloat16 h1 = __float2bfloat16(v1);
    g_w1hi[n * F + k] = h1;
    g_w1lo[n * F + k] = __float2bfloat16(v1 - __bfloat162float(h1));
    float v2 = W2[i];
    __nv_bfloat16 h2 = __float2bfloat16(v2);
    g_w2hi[n * F + k] = h2;
    g_w2lo[n * F + k] = __float2bfloat16(v2 - __bfloat162float(h2));
}

// ================= tensor GEMM: C[M,128] = A'[M,128] @ W[128,128] ================
// A fragments loaded directly from global, software-pipelined over k-steps.
#define AST    136
#define SW_HI  0
#define SW_LO  (128 * AST * 2)                 // 34816
#define SBN    (2 * 128 * AST * 2)             // 69632: 384 floats BN consts
#define MMA_SMEM (SBN + 384 * 4)               // 71168

__global__ void __launch_bounds__(256, 2)
gemm_mma(const float* __restrict__ A, int M,
         const __nv_bfloat16* __restrict__ Whi, const __nv_bfloat16* __restrict__ Wlo,
         float* __restrict__ C,
         const float* __restrict__ prebias, const float* __restrict__ aff)
{
    extern __shared__ char sm[];
    float* bnc = (float*)(sm + SBN);   // [0:128)=prebias, [128:256)=scale, [256:384)=shift
    const int tid  = threadIdx.x;
    const int lane = tid & 31;
    const int wid  = tid >> 5;
    const int m0   = blockIdx.x * 128;

    // ---- W tiles -> smem [n][k], row stride AST
    for (int i = tid; i < 2048; i += 256) {
        int n = i >> 4, kg = i & 15;
        *(uint4*)(sm + SW_HI + ((size_t)n * AST + kg * 8) * 2) = *(const uint4*)(Whi + n * 128 + kg * 8);
        *(uint4*)(sm + SW_LO + ((size_t)n * AST + kg * 8) * 2) = *(const uint4*)(Wlo + n * 128 + kg * 8);
    }
    if (prebias && tid < 128) {
        bnc[tid]       = prebias[tid];
        bnc[128 + tid] = aff[tid];
        bnc[256 + tid] = aff[F + tid];
    }
    __syncthreads();

    // warp tiling: 4 (M) x 2 (N); warp = 32 rows x 64 cols
    const int wm = (wid & 3) * 32;
    const int wn = (wid >> 2) * 64;
    uint32_t sb  = smem_to_u32(sm);
    uint32_t brw = wn + (lane >> 4) * 8 + (lane & 7);
    uint32_t bHi = sb + SW_HI + ((brw * AST + ((lane >> 3) & 1) * 8) << 1);
    uint32_t bLo = bHi + SW_LO;

    const int r0 = lane >> 2;
    const int c0 = (lane & 3) * 2;
    const int rowA = m0 + wm + r0;
    const bool ok0 = (rowA < M), ok1 = (rowA + 8 < M);
    const bool okA[2][2] = {{ok0, ok1}, {rowA + 16 < M, rowA + 24 < M}};

    float c[2][8][4];
#pragma unroll
    for (int f = 0; f < 2; f++)
#pragma unroll
        for (int j = 0; j < 8; j++)
#pragma unroll
            for (int e = 0; e < 4; e++) c[f][j][e] = 0.0f;

    const float2 Z2 = make_float2(0.f, 0.f);

    // raw fragment loads for k-step ks -> raw[f][0..3] = {(r,kc),(r+8,kc),(r,kc+8),(r+8,kc+8)}
    float2 raw[2][4];
    {
        const int kc = c0;
#pragma unroll
        for (int f = 0; f < 2; f++) {
            const float* p0 = A + (size_t)(rowA + f * 16) * 128 + kc;
            raw[f][0] = okA[f][0] ? *(const float2*)p0          : Z2;
            raw[f][1] = okA[f][1] ? *(const float2*)(p0 + 1024) : Z2;
            raw[f][2] = okA[f][0] ? *(const float2*)(p0 + 8)    : Z2;
            raw[f][3] = okA[f][1] ? *(const float2*)(p0 + 1032) : Z2;
        }
    }

    // split raw(ks) -> ah/al with optional BN transform
    uint32_t ah[2][4], al[2][4];
    auto do_split = [&](int ks, float2 (&rw)[2][4]) {
        const int kc = ks * 16 + c0;
        float2 pa, pb, sa_, sb_, ha, hb;
        if (prebias) {
            pa  = *(const float2*)(bnc + kc);        pb  = *(const float2*)(bnc + kc + 8);
            sa_ = *(const float2*)(bnc + 128 + kc);  sb_ = *(const float2*)(bnc + 128 + kc + 8);
            ha  = *(const float2*)(bnc + 256 + kc);  hb  = *(const float2*)(bnc + 256 + kc + 8);
        }
#pragma unroll
        for (int f = 0; f < 2; f++) {
            float2 v0 = rw[f][0], v1 = rw[f][1], v2 = rw[f][2], v3 = rw[f][3];
            if (prebias) {
                v0.x = fmaf(fmaxf(v0.x + pa.x, 0.f), sa_.x, ha.x);
                v0.y = fmaf(fmaxf(v0.y + pa.y, 0.f), sa_.y, ha.y);
                v1.x = fmaf(fmaxf(v1.x + pa.x, 0.f), sa_.x, ha.x);
                v1.y = fmaf(fmaxf(v1.y + pa.y, 0.f), sa_.y, ha.y);
                v2.x = fmaf(fmaxf(v2.x + pb.x, 0.f), sb_.x, hb.x);
                v2.y = fmaf(fmaxf(v2.y + pb.y, 0.f), sb_.y, hb.y);
                v3.x = fmaf(fmaxf(v3.x + pb.x, 0.f), sb_.x, hb.x);
                v3.y = fmaf(fmaxf(v3.y + pb.y, 0.f), sb_.y, hb.y);
            }
            splitpack(v0.x, v0.y, ah[f][0], al[f][0]);
            splitpack(v1.x, v1.y, ah[f][1], al[f][1]);
            splitpack(v2.x, v2.y, ah[f][2], al[f][2]);
            splitpack(v3.x, v3.y, ah[f][3], al[f][3]);
        }
    };
    do_split(0, raw);

#pragma unroll
    for (int ks = 0; ks < 8; ks++) {
        // ---- prefetch next k-step's raw A (loads issue before the MMA section)
        float2 rnext[2][4];
        if (ks < 7) {
            const int kc = (ks + 1) * 16 + c0;
#pragma unroll
            for (int f = 0; f < 2; f++) {
                const float* p0 = A + (size_t)(rowA + f * 16) * 128 + kc;
                rnext[f][0] = okA[f][0] ? *(const float2*)p0          : Z2;
                rnext[f][1] = okA[f][1] ? *(const float2*)(p0 + 1024) : Z2;
                rnext[f][2] = okA[f][0] ? *(const float2*)(p0 + 8)    : Z2;
                rnext[f][3] = okA[f][1] ? *(const float2*)(p0 + 1032) : Z2;
            }
        }

        // ---- B fragments + MMAs for current k-step
#pragma unroll
        for (int p = 0; p < 4; p++) {
            uint32_t bh[4], bl[4];
            LDSM_X4(bh, bHi + ks * 32 + p * 16 * AST * 2);
            LDSM_X4(bl, bLo + ks * 32 + p * 16 * AST * 2);
#pragma unroll
            for (int f = 0; f < 2; f++)
#pragma unroll
                for (int q = 0; q < 2; q++) {
                    int j = p * 2 + q;
                    MMA16816(c[f][j], ah[f], bh[q * 2], bh[q * 2 + 1]);
                    MMA16816(c[f][j], al[f], bh[q * 2], bh[q * 2 + 1]);
                    MMA16816(c[f][j], ah[f], bl[q * 2], bl[q * 2 + 1]);
                }
        }

        // ---- split next (loads have had the MMA section to land)
        if (ks < 7) do_split(ks + 1, rnext);
    }

    // ---- epilogue
    const int cc = (lane & 3) * 2;
#pragma unroll
    for (int f = 0; f < 2; f++) {
        int row = m0 + wm + f * 16 + r0;
#pragma unroll
        for (int j = 0; j < 8; j++) {
            int col = wn + j * 8 + cc;
            if (row < M)
                *(float2*)(C + (size_t)row * 128 + col) = make_float2(c[f][j][0], c[f][j][1]);
            if (row + 8 < M)
                *(float2*)(C + (size_t)(row + 8) * 128 + col) = make_float2(c[f][j][2], c[f][j][3]);
        }
    }
}

// ================= gather (CSR, no atomics) + fused BN stats =====================
__global__ void gather_kernel(const float* __restrict__ h, float* __restrict__ agg,
                              const float* __restrict__ bias, float* __restrict__ sums)
{
    __shared__ float ss[256];
    int tid = threadIdx.x;                       // 512 threads = 16 warps = 16 nodes
    if (tid < 256) ss[tid] = 0.0f;
    __syncthreads();

    int node = blockIdx.x * 16 + (tid >> 5);
    int lane = tid & 31;

    if (node < NNODES) {
        int beg = g_csr_ptr[node];
        int end = g_csr_ptr[node + 1];
        float di = g_dinv[node];
        const float4* hv = (const float4*)h;
        float4 acc = hv[(size_t)node * 32 + lane];
        float sn = di * di;
        acc.x *= sn; acc.y *= sn; acc.z *= sn; acc.w *= sn;
        int e = beg;
        // unroll 4: four concurrent row loads (MLP=4 vs L2 latency)
        for (; e + 3 < end; e += 4) {
            int s0 = __ldg(&g_csr_src[e]);
            int s1 = __ldg(&g_csr_src[e + 1]);
            int s2 = __ldg(&g_csr_src[e + 2]);
            int s3 = __ldg(&g_csr_src[e + 3]);
            float n0 = di * g_dinv[s0];
            float n1 = di * g_dinv[s1];
            float n2 = di * g_dinv[s2];
            float n3 = di * g_dinv[s3];
            float4 v0 = hv[(size_t)s0 * 32 + lane];
            float4 v1 = hv[(size_t)s1 * 32 + lane];
            float4 v2 = hv[(size_t)s2 * 32 + lane];
            float4 v3 = hv[(size_t)s3 * 32 + lane];
            acc.x = fmaf(v0.x, n0, acc.x); acc.y = fmaf(v0.y, n0, acc.y);
            acc.z = fmaf(v0.z, n0, acc.z); acc.w = fmaf(v0.w, n0, acc.w);
            acc.x = fmaf(v1.x, n1, acc.x); acc.y = fmaf(v1.y, n1, acc.y);
            acc.z = fmaf(v1.z, n1, acc.z); acc.w = fmaf(v1.w, n1, acc.w);
            acc.x = fmaf(v2.x, n2, acc.x); acc.y = fmaf(v2.y, n2, acc.y);
            acc.z = fmaf(v2.z, n2, acc.z); acc.w = fmaf(v2.w, n2, acc.w);
            acc.x = fmaf(v3.x, n3, acc.x); acc.y = fmaf(v3.y, n3, acc.y);
            acc.z = fmaf(v3.z, n3, acc.z); acc.w = fmaf(v3.w, n3, acc.w);
        }
        for (; e < end; e++) {
            int s0 = __ldg(&g_csr_src[e]);
            float n0 = di * g_dinv[s0];
            float4 v0 = hv[(size_t)s0 * 32 + lane];
            acc.x = fmaf(v0.x, n0, acc.x); acc.y = fmaf(v0.y, n0, acc.y);
            acc.z = fmaf(v0.z, n0, acc.z); acc.w = fmaf(v0.w, n0, acc.w);
        }
        ((float4*)agg)[(size_t)node * 32 + lane] = acc;

        int d = lane * 4;
        float v0 = fmaxf(acc.x + bias[d + 0], 0.0f);
        float v1 = fmaxf(acc.y + bias[d + 1], 0.0f);
        float v2 = fmaxf(acc.z + bias[d + 2], 0.0f);
        float v3 = fmaxf(acc.w + bias[d + 3], 0.0f);
        atomicAdd(&ss[d + 0], v0);  atomicAdd(&ss[128 + d + 0], v0 * v0);
        atomicAdd(&ss[d + 1], v1);  atomicAdd(&ss[128 + d + 1], v1 * v1);
        atomicAdd(&ss[d + 2], v2);  atomicAdd(&ss[128 + d + 2], v2 * v2);
        atomicAdd(&ss[d + 3], v3);  atomicAdd(&ss[128 + d + 3], v3 * v3);
    }
    __syncthreads();
    if (tid < 256) atomicAdd(&sums[tid], ss[tid]);
}

// ================= BN finalize / stats / apply ===================================
__global__ void finalize_kernel(const float* __restrict__ sums, float invM,
                                const float* __restrict__ gamma, const float* __restrict__ beta,
                                float* __restrict__ aff)
{
    int d = threadIdx.x;
    float m = sums[d] * invM;
    float var = sums[F + d] * invM - m * m;
    float r = rsqrtf(var + BN_EPS);
    float sc = gamma[d] * r;
    aff[d]     = sc;
    aff[F + d] = beta[d] - sc * m;
}

__global__ void bn_stats_kernel(const float* __restrict__ in, float* __restrict__ sums, int M) {
    int d = threadIdx.x;
    float s = 0.0f, q = 0.0f;
    for (int r = blockIdx.x; r < M; r += gridDim.x) {
        float v = in[(size_t)r * F + d];
        s += v; q += v * v;
    }
    atomicAdd(&sums[d], s);
    atomicAdd(&sums[F + d], q);
}

__global__ void bn_apply_kernel(const float* __restrict__ in, const float* __restrict__ sums,
                                const float* __restrict__ gamma, const float* __restrict__ beta,
                                float* __restrict__ out, int M)
{
    int i = blockIdx.x * blockDim.x + threadIdx.x;
    if (i >= M * F) return;
    int d = i & 127;
    float invM = 1.0f / (float)M;
    float m   = sums[d] * invM;
    float var = sums[F + d] * invM - m * m;
    out[i] = gamma[d] * (in[i] - m) * rsqrtf(var + BN_EPS) + beta[d];
}

// ================= SIMT GEMM (cell branch only) =================================
__global__ __launch_bounds__(256) void gemm128(
    const float* __restrict__ A, const float* __restrict__ B,
    const float* __restrict__ bias, float* __restrict__ C,
    int M, int K, int act)
{
    __shared__ float As[16][132];
    __shared__ float Bs[16][128];
    const int tid = threadIdx.x;
    const int m0  = blockIdx.x * 128;
    const int tn  = tid & 15;
    const int tm  = tid >> 4;
    float acc[8][8];
#pragma unroll
    for (int i = 0; i < 8; i++)
#pragma unroll
        for (int j = 0; j < 8; j++) acc[i][j] = 0.0f;
    const int arow = tid >> 4, acol = tid & 15;
    const int brow = tid >> 7, bcol = tid & 127;
    for (int kk = 0; kk < K; kk += 16) {
#pragma unroll
        for (int p = 0; p < 8; p++) {
            int m = p * 16 + arow, gk = kk + acol, gm = m0 + m;
            float v = 0.0f;
            if (gm < M && gk < K) v = A[(size_t)gm * K + gk];
            As[acol][m] = v;
        }
#pragma unroll
        for (int q = 0; q < 8; q++) {
            int k = q * 2 + brow, gk = kk + k;
            Bs[k][bcol] = (gk < K) ? B[(size_t)gk * 128 + bcol] : 0.0f;
        }
        __syncthreads();
#pragma unroll
        for (int k = 0; k < 16; k++) {
            float4 a0 = *(const float4*)&As[k][tm * 8];
            float4 a1 = *(const float4*)&As[k][tm * 8 + 4];
            float4 b0 = *(const float4*)&Bs[k][tn * 8];
            float4 b1 = *(const float4*)&Bs[k][tn * 8 + 4];
            float a[8] = {a0.x, a0.y, a0.z, a0.w, a1.x, a1.y, a1.z, a1.w};
            float b[8] = {b0.x, b0.y, b0.z, b0.w, b1.x, b1.y, b1.z, b1.w};
#pragma unroll
            for (int i = 0; i < 8; i++)
#pragma unroll
                for (int j = 0; j < 8; j++)
                    acc[i][j] = fmaf(a[i], b[j], acc[i][j]);
        }
        __syncthreads();
    }
#pragma unroll
    for (int i = 0; i < 8; i++) {
        int gm = m0 + tm * 8 + i;
        if (gm >= M) continue;
        float o[8];
#pragma unroll
        for (int j = 0; j < 8; j++) {
            float v = acc[i][j] + bias[tn * 8 + j];
            if (act == 1)      v = fmaxf(v, 0.0f);
            else if (act == 2) v = tanhf(v);
            o[j] = v;
        }
        float4* cp = (float4*)&C[(size_t)gm * 128 + tn * 8];
        cp[0] = make_float4(o[0], o[1], o[2], o[3]);
        cp[1] = make_float4(o[4], o[5], o[6], o[7]);
    }
}

// ================= segment bounds + fused bn+segmax ==============================
__global__ void bounds_kernel(const int* __restrict__ ib) {
    int i = blockIdx.x * blockDim.x + threadIdx.x;
    if (i >= NNODES) return;
    if (i == 0) { g_start[ib[0]] = 0; g_start[NG] = NNODES; }
    else {
        int g = ib[i];
        if (ib[i - 1] != g) g_start[g] = i;
    }
}

__global__ void segmax_kernel(const float* __restrict__ h, const float* __restrict__ bias,
                              const float* __restrict__ aff, float* __restrict__ out)
{
    int idx = blockIdx.x * blockDim.x + threadIdx.x;
    if (idx >= NG * F) return;
    int g = idx >> 7, d = idx & 127;
    int s = g_start[g], e = g_start[g + 1];
    float b = bias[d], sc = aff[d], sh = aff[F + d];
    float m = -3.402823466e38f;
    for (int r = s; r < e; r++) {
        float v = fmaxf(h[(size_t)r * F + d] + b, 0.0f);
        m = fmaxf(m, fmaf(v, sc, sh));
    }
    out[idx] = m;
}

// ================= launch ========================================================
extern "C" void kernel_launch(void* const* d_in, const int* in_sizes, int n_in,
                              void* d_out, int out_size)
{
    const float* x      = (const float*)d_in[0];
    const int*   eidx   = (const int*)  d_in[1];
    const int*   ibatch = (const int*)  d_in[2];
    const float* gexpr  = (const float*)d_in[3];
    const float* W1  = (const float*)d_in[4];
    const float* b1  = (const float*)d_in[5];
    const float* g1  = (const float*)d_in[6];
    const float* be1 = (const float*)d_in[7];
    const float* W2  = (const float*)d_in[8];
    const float* b2  = (const float*)d_in[9];
    const float* g2  = (const float*)d_in[10];
    const float* be2 = (const float*)d_in[11];
    const float* Wc1 = (const float*)d_in[12];
    const float* bc1 = (const float*)d_in[13];
    const float* gc  = (const float*)d_in[14];
    const float* bec = (const float*)d_in[15];
    const float* Wc2 = (const float*)d_in[16];
    const float* bc2 = (const float*)d_in[17];
    float* out = (float*)d_out;

    const int* src = eidx;
    const int* dst = eidx + NEDGES;

    float* bufA; cudaGetSymbolAddress((void**)&bufA, g_bufA);
    float* bufB; cudaGetSymbolAddress((void**)&bufB, g_bufB);
    float* cell; cudaGetSymbolAddress((void**)&cell, g_cell);
    float* sums; cudaGetSymbolAddress((void**)&sums, g_sums);
    float* aff;  cudaGetSymbolAddress((void**)&aff,  g_aff);
    __nv_bfloat16 *w1hi, *w1lo, *w2hi, *w2lo;
    cudaGetSymbolAddress((void**)&w1hi, g_w1hi);
    cudaGetSymbolAddress((void**)&w1lo, g_w1lo);
    cudaGetSymbolAddress((void**)&w2hi, g_w2hi);
    cudaGetSymbolAddress((void**)&w2lo, g_w2lo);

    cudaFuncSetAttribute(gemm_mma, cudaFuncAttributeMaxDynamicSharedMemorySize, MMA_SMEM);

    static cudaStream_t s_csr = nullptr, s_cell = nullptr;
    static cudaEvent_t ev_root = nullptr, ev_csr = nullptr, ev_cell = nullptr;
    if (!s_csr) {
        cudaStreamCreateWithFlags(&s_csr,  cudaStreamNonBlocking);
        cudaStreamCreateWithFlags(&s_cell, cudaStreamNonBlocking);
        cudaEventCreateWithFlags(&ev_root, cudaEventDisableTiming);
        cudaEventCreateWithFlags(&ev_csr,  cudaEventDisableTiming);
        cudaEventCreateWithFlags(&ev_cell, cudaEventDisableTiming);
    }

    const int T = 256;
    int gN  = (NNODES + T - 1) / T;
    int gE  = (NEDGES + T - 1) / T;
    int gGF = (NG * F + T - 1) / T;
    int gGather = (NNODES + 15) / 16;
    int gTile   = (NNODES + 127) / 128;
    int gGemmG  = (NG + 127) / 128;

    // ---- fork
    cudaEventRecord(ev_root, 0);
    cudaStreamWaitEvent(s_csr,  ev_root, 0);
    cudaStreamWaitEvent(s_cell, ev_root, 0);

    // submissions 1-4: init, deg, wprep, gemm_mma (gemm_mma lands in ncu's profile slot)
    init_kernel<<<gN, T, 0, s_csr>>>();
    deg_kernel<<<gE, T, 0, s_csr>>>(dst);
    wprep_kernel<<<(F * F + 255) / 256, 256>>>(W1, W2);
    gemm_mma<<<gTile, 256, MMA_SMEM>>>(x, NNODES, w1hi, w1lo, bufA, nullptr, nullptr);

    // ---- rest of CSR branch (s_csr)
    dinv_kernel<<<gN, T, 0, s_csr>>>();
    scan1_kernel<<<NBLK, 256, 0, s_csr>>>();
    scan2_kernel<<<1, 1024, 0, s_csr>>>();
    scan3_kernel<<<gN, T, 0, s_csr>>>();
    fill_kernel<<<gE, T, 0, s_csr>>>(src, dst);
    bounds_kernel<<<gN, T, 0, s_csr>>>(ibatch);
    cudaEventRecord(ev_csr, s_csr);

    // ---- cell branch (s_cell)
    zero_cell_sums<<<1, 256, 0, s_cell>>>();
    gemm128<<<gGemmG, 256, 0, s_cell>>>(gexpr, Wc1, bc1, cell, NG, DCELL, 2);
    bn_stats_kernel<<<512, 128, 0, s_cell>>>(cell, sums + 512, NG);
    bn_apply_kernel<<<gGF, T, 0, s_cell>>>(cell, sums + 512, gc, bec, cell, NG);
    gemm128<<<gGemmG, 256, 0, s_cell>>>(cell, Wc2, bc2, out + (size_t)NG * F, NG, 128, 1);
    cudaEventRecord(ev_cell, s_cell);

    // ---- main: join CSR, then aggregation pipeline
    cudaStreamWaitEvent(0, ev_csr, 0);
    gather_kernel<<<gGather, 512>>>(bufA, bufB, b1, sums + 0);
    finalize_kernel<<<1, 128>>>(sums + 0, 1.0f / NNODES, g1, be1, aff + 0);

    gemm_mma<<<gTile, 256, MMA_SMEM>>>(bufB, NNODES, w2hi, w2lo, bufA, b1, aff + 0);
    gather_kernel<<<gGather, 512>>>(bufA, bufB, b2, sums + 256);
    finalize_kernel<<<1, 128>>>(sums + 256, 1.0f / NNODES, g2, be2, aff + 256);

    segmax_kernel<<<gGF, T>>>(bufB, b2, aff + 256, out);

    // ---- join cell branch
    cudaStreamWaitEvent(0, ev_cell, 0);
}